// round 4
// baseline (speedup 1.0000x reference)
#include <cuda_runtime.h>
#include <cstdint>

// Problem constants (fixed by the dataset)
#define B_   16
#define MC   2048
#define MT   4096
#define E_   512
#define NHOP 2

#define NROW_H (B_ * MC)   // 32768
#define NROW_R (B_ * MT)   // 65536

// ---------------- scratch (static device globals; no allocation allowed) ---
__device__ float g_h  [NROW_H * E_];
__device__ float g_h2 [NROW_H * E_];
__device__ float g_upd[NROW_H * E_];
__device__ float g_r  [NROW_R * E_];
__device__ float g_r2 [NROW_R * E_];
__device__ float g_cnt[NROW_H];

// ---------------- gather: out[row] = table[ids[row]] ------------------------
__global__ void gather_rows(const float* __restrict__ table,
                            const int* __restrict__ ids,
                            float* __restrict__ out) {
    const int row = blockIdx.x;
    const int id  = ids[row];
    const float4* src = (const float4*)(table + (size_t)id * E_);
    float4*       dst = (float4*)(out + (size_t)row * E_);
    dst[threadIdx.x] = src[threadIdx.x];          // 128 threads * float4 = 512 f
}

// ---------------- scatter messages + degree counts (vector red) -------------
__device__ __forceinline__ void red4(float* p, float a, float b, float c, float d) {
    asm volatile("red.global.add.v4.f32 [%0], {%1, %2, %3, %4};"
                 :: "l"(p), "f"(a), "f"(b), "f"(c), "f"(d) : "memory");
}

__global__ void scatter_upd(const int* __restrict__ head,
                            const int* __restrict__ tail,
                            const int* __restrict__ labels,
                            const float* __restrict__ h,
                            const float* __restrict__ r,
                            float* __restrict__ upd,
                            float* __restrict__ cnt) {
    const int t = blockIdx.x;
    if (labels[t] == -1) return;
    const int b  = t / MT;
    const size_t rowh = (size_t)b * MC + head[t];
    const size_t rowt = (size_t)b * MC + tail[t];

    const float4* hh = (const float4*)(h + rowh * E_);
    const float4* ht = (const float4*)(h + rowt * E_);
    const float4* rr = (const float4*)(r + (size_t)t * E_);
    float* ut = upd + rowt * E_;
    float* uh = upd + rowh * E_;

    const int i = threadIdx.x;
    float4 hv = hh[i];
    float4 tv = ht[i];
    float4 rv = rr[i];
    const int o = 4 * i;
    red4(ut + o, hv.x - rv.x, hv.y - rv.y, hv.z - rv.z, hv.w - rv.w);
    red4(uh + o, tv.x - rv.x, tv.y - rv.y, tv.z - rv.z, tv.w - rv.w);
    if (i == 0) {
        atomicAdd(cnt + rowt, 1.0f);
        atomicAdd(cnt + rowh, 1.0f);
    }
}

// ---------------- tf32 helpers ----------------------------------------------
__device__ __forceinline__ uint32_t f2tf32(float x) {
    uint32_t r;
    asm volatile("cvt.rna.tf32.f32 %0, %1;" : "=r"(r) : "f"(x));
    return r;
}

__device__ __forceinline__ void mma_tf32(float* c, const uint32_t* a, const uint32_t* b) {
    asm volatile(
        "mma.sync.aligned.m16n8k8.row.col.f32.tf32.tf32.f32 "
        "{%0,%1,%2,%3}, {%4,%5,%6,%7}, {%8,%9}, {%0,%1,%2,%3};\n"
        : "+f"(c[0]), "+f"(c[1]), "+f"(c[2]), "+f"(c[3])
        : "r"(a[0]), "r"(a[1]), "r"(a[2]), "r"(a[3]), "r"(b[0]), "r"(b[1]));
}

// ==================== tf32 tensor-core GEMM NT ====================
// C[m,n] = sum_src sum_k A_src[m,k] * W_src[n,k],  K = 512 per source.
// CTA tile 128x256, BK=16, double buffered, 256 threads (8 warps, each 32x128).
// The second source's A rows are scaled by 1/clip(cnt,1) at load time (fuses
// the scale_upd kernel). Shared tiles are stored in *fragment order* so both
// STS and LDS are conflict-free vector ops.
//   A slot: [(mf*2+ks)*32 + lane] -> 4 regs (uint4)
//   B slot: [(nf*2+ks)*32 + lane] -> 2 regs (uint2)
template<int NSRC, bool RELU>
__global__ __launch_bounds__(256)
void gemm_tf32(const float* __restrict__ A0, const float* __restrict__ W0,
               const float* __restrict__ A1, const float* __restrict__ W1,
               const float* __restrict__ cnt, float* __restrict__ C) {
    constexpr int LD = E_;
    constexpr int KT = E_ / 16;               // 32 K-slices per source
    constexpr int TOTAL = NSRC * KT;

    __shared__ uint32_t Asm[2][2048];          // 128x16 tf32, fragment order
    __shared__ uint32_t Bsm[2][4096];          // 256x16 tf32, fragment order

    const int tid  = threadIdx.x;
    const int lane = tid & 31;
    const int wq   = tid >> 5;                 // warp 0..7
    const int wm   = (wq >> 1) * 32;           // warp row base (4 row groups)
    const int wn   = (wq & 1) * 128;           // warp col base (2 col groups)
    const int bm   = blockIdx.y * 128;
    const int bn   = blockIdx.x * 256;

    // ---- loader geometry (t-invariant) ----
    // A: 16 fragment blocks, warp covers blk = wq + 8*i (i=0..1)
    // B: 64 fragment blocks, warp covers blk = wq + 8*j (j=0..7)
    int aoff[2];
    float s[2][2];                             // per-row 1/clip(cnt) for src1
    #pragma unroll
    for (int i = 0; i < 2; ++i) {
        const int blk = wq + 8 * i;
        const int m = (blk >> 1) * 16 + (lane >> 2);
        const int k = (blk & 1) * 8 + (lane & 3);
        aoff[i] = m * LD + k;
        if (NSRC == 2) {
            s[i][0] = 1.0f / fmaxf(cnt[bm + m], 1.0f);
            s[i][1] = 1.0f / fmaxf(cnt[bm + m + 8], 1.0f);
        }
    }
    int boff[8];
    #pragma unroll
    for (int j = 0; j < 8; ++j) {
        const int blk = wq + 8 * j;
        const int n = (blk >> 1) * 8 + (lane >> 2);
        const int k = (blk & 1) * 8 + (lane & 3);
        boff[j] = n * LD + k;
    }

    float la[2][4];
    float lb[8][2];

    float acc[2][16][4];
    #pragma unroll
    for (int f = 0; f < 2; ++f)
        #pragma unroll
        for (int g = 0; g < 16; ++g)
            #pragma unroll
            for (int e = 0; e < 4; ++e) acc[f][g][e] = 0.0f;

    auto ldg_tile = [&](int t) {
        const bool second = (NSRC == 2) && (t >= KT);
        const float* A = second ? A1 : A0;
        const float* W = second ? W1 : W0;
        const int kg = (t & (KT - 1)) * 16;
        const float* Ab = A + (size_t)bm * LD + kg;
        const float* Wb = W + (size_t)bn * LD + kg;
        #pragma unroll
        for (int i = 0; i < 2; ++i) {
            la[i][0] = Ab[aoff[i]];
            la[i][1] = Ab[aoff[i] + 8 * LD];
            la[i][2] = Ab[aoff[i] + 4];
            la[i][3] = Ab[aoff[i] + 8 * LD + 4];
            if (second) {                      // fused scale_upd
                la[i][0] *= s[i][0];
                la[i][1] *= s[i][1];
                la[i][2] *= s[i][0];
                la[i][3] *= s[i][1];
            }
        }
        #pragma unroll
        for (int j = 0; j < 8; ++j) {
            lb[j][0] = Wb[boff[j]];
            lb[j][1] = Wb[boff[j] + 4];
        }
    };

    auto sts_tile = [&](int buf) {
        #pragma unroll
        for (int i = 0; i < 2; ++i) {
            const int blk = wq + 8 * i;
            uint4 v;
            v.x = f2tf32(la[i][0]);
            v.y = f2tf32(la[i][1]);
            v.z = f2tf32(la[i][2]);
            v.w = f2tf32(la[i][3]);
            *(uint4*)&Asm[buf][(blk * 32 + lane) * 4] = v;
        }
        #pragma unroll
        for (int j = 0; j < 8; ++j) {
            const int blk = wq + 8 * j;
            uint2 v;
            v.x = f2tf32(lb[j][0]);
            v.y = f2tf32(lb[j][1]);
            *(uint2*)&Bsm[buf][(blk * 32 + lane) * 2] = v;
        }
    };

    auto compute = [&](int buf) {
        #pragma unroll
        for (int ks = 0; ks < 2; ++ks) {
            uint4 afr[2];
            #pragma unroll
            for (int f = 0; f < 2; ++f)
                afr[f] = *(const uint4*)&Asm[buf][(((wm >> 4) + f) * 2 + ks) * 128 + lane * 4];
            #pragma unroll
            for (int g0 = 0; g0 < 16; g0 += 4) {    // chunk B frags to bound live regs
                uint2 bfr[4];
                #pragma unroll
                for (int g = 0; g < 4; ++g)
                    bfr[g] = *(const uint2*)&Bsm[buf][(((wn >> 3) + g0 + g) * 2 + ks) * 64 + lane * 2];
                #pragma unroll
                for (int f = 0; f < 2; ++f)
                    #pragma unroll
                    for (int g = 0; g < 4; ++g)
                        mma_tf32(acc[f][g0 + g], (const uint32_t*)&afr[f], (const uint32_t*)&bfr[g]);
            }
        }
    };

    // ---- pipeline ----
    ldg_tile(0);
    sts_tile(0);
    __syncthreads();
    for (int t = 0; t < TOTAL; ++t) {
        const int buf = t & 1;
        if (t + 1 < TOTAL) ldg_tile(t + 1);
        compute(buf);
        if (t + 1 < TOTAL) {
            sts_tile(buf ^ 1);
            __syncthreads();
        }
    }

    // ---- epilogue: warp tile 32x128 ----
    #pragma unroll
    for (int f = 0; f < 2; ++f) {
        #pragma unroll
        for (int g = 0; g < 16; ++g) {
            const int row0 = bm + wm + f * 16 + (lane >> 2);
            const int col  = bn + wn + g * 8 + (lane & 3) * 2;
            float2 v0 = make_float2(acc[f][g][0], acc[f][g][1]);
            float2 v1 = make_float2(acc[f][g][2], acc[f][g][3]);
            if (RELU) {
                v0.x = fmaxf(v0.x, 0.f); v0.y = fmaxf(v0.y, 0.f);
                v1.x = fmaxf(v1.x, 0.f); v1.y = fmaxf(v1.y, 0.f);
            }
            *(float2*)&C[(size_t)row0 * LD + col]       = v0;
            *(float2*)&C[(size_t)(row0 + 8) * LD + col] = v1;
        }
    }
}

// ---------------- final concat: out[t] = [h[head], r, h[tail]] --------------
__global__ void final_gather(const float* __restrict__ h,
                             const float* __restrict__ r,
                             const int* __restrict__ head,
                             const int* __restrict__ tail,
                             float* __restrict__ out) {
    const int t = blockIdx.x;
    const int b = t / MT;
    const float4* hh = (const float4*)(h + ((size_t)b * MC + head[t]) * E_);
    const float4* ht = (const float4*)(h + ((size_t)b * MC + tail[t]) * E_);
    const float4* rr = (const float4*)(r + (size_t)t * E_);
    float4* o = (float4*)(out + (size_t)t * 3 * E_);
    const int i = threadIdx.x;
    o[i]       = hh[i];
    o[128 + i] = rr[i];
    o[256 + i] = ht[i];
}

// ---------------- host launch ------------------------------------------------
extern "C" void kernel_launch(void* const* d_in, const int* in_sizes, int n_in,
                              void* d_out, int out_size) {
    const float* concept_table  = (const float*)d_in[0];
    const float* relation_table = (const float*)d_in[1];
    const float* W_s            = (const float*)d_in[2];
    const float* W_n            = (const float*)d_in[3];
    const float* W_r            = (const float*)d_in[4];
    const int*   concept_ids    = (const int*)d_in[5];
    const int*   relation_ids   = (const int*)d_in[6];
    const int*   head_idx       = (const int*)d_in[7];
    const int*   tail_idx       = (const int*)d_in[8];
    const int*   labels         = (const int*)d_in[9];
    float*       out            = (float*)d_out;

    float *h, *h2, *r, *r2, *upd, *cnt;
    cudaGetSymbolAddress((void**)&h,   g_h);
    cudaGetSymbolAddress((void**)&h2,  g_h2);
    cudaGetSymbolAddress((void**)&r,   g_r);
    cudaGetSymbolAddress((void**)&r2,  g_r2);
    cudaGetSymbolAddress((void**)&upd, g_upd);
    cudaGetSymbolAddress((void**)&cnt, g_cnt);

    gather_rows<<<NROW_H, 128>>>(concept_table, concept_ids, h);   // launch 0
    gather_rows<<<NROW_R, 128>>>(relation_table, relation_ids, r); // launch 1

    float* hc = h;  float* hn = h2;
    float* rc = r;  float* rn = r2;

    const size_t MAT = (size_t)E_ * E_;

    for (int l = 0; l < NHOP; ++l) {
        cudaMemsetAsync(upd, 0, sizeof(float) * (size_t)NROW_H * E_);  // 2
        cudaMemsetAsync(cnt, 0, sizeof(float) * (size_t)NROW_H);       // 3

        scatter_upd<<<NROW_R, 128>>>(head_idx, tail_idx, labels, hc, rc, upd, cnt); // 4

        const float* Ws = W_s + (size_t)l * MAT;
        const float* Wn = W_n + (size_t)l * MAT;
        const float* Wr = W_r + (size_t)l * MAT;

        dim3 gh(E_ / 256, NROW_H / 128);           // (2, 256)
        dim3 gr(E_ / 256, NROW_R / 128);           // (2, 512)
        // launch 5 on hop 0 -> ncu captures this GEMM
        gemm_tf32<2, true ><<<gh, 256>>>(hc, Ws, upd, Wn, cnt, hn);
        gemm_tf32<1, false><<<gr, 256>>>(rc, Wr, rc, Wr, (const float*)nullptr, rn);

        float* tmp;
        tmp = hc; hc = hn; hn = tmp;
        tmp = rc; rc = rn; rn = tmp;
    }

    final_gather<<<NROW_R, 128>>>(hc, rc, head_idx, tail_idx, out);
}

// round 5
// speedup vs baseline: 1.3643x; 1.3643x over previous
#include <cuda_runtime.h>
#include <cstdint>

// Problem constants (fixed by the dataset)
#define B_   16
#define MC   2048
#define MT   4096
#define E_   512
#define NHOP 2

#define NROW_H (B_ * MC)   // 32768
#define NROW_R (B_ * MT)   // 65536
#define MAT    (E_ * E_)   // 262144

// ---------------- scratch (static device globals; no allocation allowed) ---
__device__ float g_h  [NROW_H * E_];
__device__ float g_h2 [NROW_H * E_];
__device__ float g_upd[NROW_H * E_ + NROW_H];   // cnt lives in the tail
__device__ float g_r  [NROW_R * E_];
__device__ float g_r2 [NROW_R * E_];
__device__ float g_wf [6 * MAT];                // frag-order tf32 weights
                                                // [Ws0,Ws1,Wn0,Wn1,Wr0,Wr1]

// ---------------- tf32 helper ------------------------------------------------
__device__ __forceinline__ uint32_t f2tf32(float x) {
    uint32_t r;
    asm volatile("cvt.rna.tf32.f32 %0, %1;" : "=r"(r) : "f"(x));
    return r;
}

__device__ __forceinline__ void mma_tf32(float* c, const uint32_t* a, const uint32_t* b) {
    asm volatile(
        "mma.sync.aligned.m16n8k8.row.col.f32.tf32.tf32.f32 "
        "{%0,%1,%2,%3}, {%4,%5,%6,%7}, {%8,%9}, {%0,%1,%2,%3};\n"
        : "+f"(c[0]), "+f"(c[1]), "+f"(c[2]), "+f"(c[3])
        : "r"(a[0]), "r"(a[1]), "r"(a[2]), "r"(a[3]), "r"(b[0]), "r"(b[1]));
}

// ---------------- gather: out[row] = table[ids[row]] ------------------------
__global__ void gather_rows(const float* __restrict__ table,
                            const int* __restrict__ ids,
                            float* __restrict__ out) {
    const int row = blockIdx.x;
    const int id  = ids[row];
    const float4* src = (const float4*)(table + (size_t)id * E_);
    float4*       dst = (float4*)(out + (size_t)row * E_);
    dst[threadIdx.x] = src[threadIdx.x];
}

// ---------------- weight pre-transform: row-major -> fragment order ---------
// B-fragment layout (per 256-col panel, per 16-wide K slice):
//   word = (panel*32 + slice)*4096 + (blk*32 + lane)*2 + reg
//   blk = (nl>>3)*2 + (kl>>3), lane = (nl&7)*4 + (kl&3), reg = (kl>>2)&1
__global__ void frag_weights(const float* __restrict__ Ws,
                             const float* __restrict__ Wn,
                             const float* __restrict__ Wr,
                             float* __restrict__ dst) {
    const int idx = blockIdx.x * 256 + threadIdx.x;   // 6 * 262144 total
    const int mat = idx >> 18;
    const int rem = idx & (MAT - 1);
    const int n = rem >> 9;
    const int k = rem & 511;
    const float* src = (mat < 2) ? Ws + (size_t)mat * MAT
                     : (mat < 4) ? Wn + (size_t)(mat - 2) * MAT
                                 : Wr + (size_t)(mat - 4) * MAT;
    const float v = __uint_as_float(f2tf32(src[rem]));
    const int panel = n >> 8, nl = n & 255;
    const int s = k >> 4, kl = k & 15;
    const int blk  = (nl >> 3) * 2 + (kl >> 3);
    const int lane = (nl & 7) * 4 + (kl & 3);
    const int reg  = (kl >> 2) & 1;
    dst[(size_t)mat * MAT + (panel * 32 + s) * 4096 + (blk * 32 + lane) * 2 + reg] = v;
}

// ---------------- scatter messages + degree counts (vector red) -------------
__device__ __forceinline__ void red4(float* p, float a, float b, float c, float d) {
    asm volatile("red.global.add.v4.f32 [%0], {%1, %2, %3, %4};"
                 :: "l"(p), "f"(a), "f"(b), "f"(c), "f"(d) : "memory");
}

__global__ void scatter_upd(const int* __restrict__ head,
                            const int* __restrict__ tail,
                            const int* __restrict__ labels,
                            const float* __restrict__ h,
                            const float* __restrict__ r,
                            float* __restrict__ upd,
                            float* __restrict__ cnt) {
    const int t = blockIdx.x;
    if (labels[t] == -1) return;
    const int b  = t / MT;
    const size_t rowh = (size_t)b * MC + head[t];
    const size_t rowt = (size_t)b * MC + tail[t];

    const float4* hh = (const float4*)(h + rowh * E_);
    const float4* ht = (const float4*)(h + rowt * E_);
    const float4* rr = (const float4*)(r + (size_t)t * E_);
    float* ut = upd + rowt * E_;
    float* uh = upd + rowh * E_;

    const int i = threadIdx.x;
    float4 hv = hh[i];
    float4 tv = ht[i];
    float4 rv = rr[i];
    const int o = 4 * i;
    red4(ut + o, hv.x - rv.x, hv.y - rv.y, hv.z - rv.z, hv.w - rv.w);
    red4(uh + o, tv.x - rv.x, tv.y - rv.y, tv.z - rv.z, tv.w - rv.w);
    if (i == 0) {
        atomicAdd(cnt + rowt, 1.0f);
        atomicAdd(cnt + rowh, 1.0f);
    }
}

// ==================== tf32 tensor-core GEMM NT ====================
// C[m,n] = sum_src sum_k A_src[m,k] * W_src[n,k],  K = 512 per source.
// CTA 128x256, BK=16, double-buffered, 512 threads = 16 warps (4x4 grid of
// 32x64 warp tiles). A staged coalesced (LDG.128 row-major) into XOR-swizzled
// smem; fragments via conflict-free LDS.32. B pre-transformed to fragment
// order in gmem: LDG.128 -> identity STS.128 -> LDS.64 fragments.
// Second A source rows scaled by 1/clip(cnt,1) at staging (fused scale_upd).
template<int NSRC, bool RELU>
__global__ __launch_bounds__(512, 1)
void gemm_tf32(const float* __restrict__ A0, const float* __restrict__ Wf0,
               const float* __restrict__ A1, const float* __restrict__ Wf1,
               const float* __restrict__ cnt, float* __restrict__ C) {
    constexpr int KT = E_ / 16;                // 32 K-slices per source
    constexpr int TOTAL = NSRC * KT;

    __shared__ uint32_t As[2][2048];           // 128x16 tf32, swizzled row-major
    __shared__ uint32_t Bs[2][4096];           // 256x16 tf32, fragment order

    const int tid  = threadIdx.x;
    const int lane = tid & 31;
    const int wq   = tid >> 5;                 // warp 0..15
    const int wm   = (wq >> 2) * 32;           // warp row base
    const int wn   = (wq & 3) * 64;            // warp col base
    const int bm   = blockIdx.y * 128;
    const int bn   = blockIdx.x * 256;         // panel = blockIdx.x

    // ---- A staging geometry: thread owns one (row, 16B-quad) per tile ----
    const int arow = tid >> 2;                 // 0..127
    const int aq   = tid & 3;
    const int asw  = arow * 16 + ((aq ^ ((arow >> 1) & 3)) << 2);  // swizzled word
    const float* Ar0 = A0 + (size_t)(bm + arow) * E_ + aq * 4;
    const float* Ar1 = (NSRC == 2) ? (A1 + (size_t)(bm + arow) * E_ + aq * 4) : nullptr;
    const float  sc  = (NSRC == 2) ? (1.0f / fmaxf(cnt[bm + arow], 1.0f)) : 1.0f;

    // ---- B staging: thread owns words [tid*8, tid*8+8) of the 16KB slice ----
    const float* Bp0 = Wf0 + (size_t)blockIdx.x * 32 * 4096 + tid * 8;
    const float* Bp1 = (NSRC == 2) ? (Wf1 + (size_t)blockIdx.x * 32 * 4096 + tid * 8) : nullptr;

    // ---- fragment LDS base addresses (ks=0, quad-xor applied later) ----
    int abase[2];
    #pragma unroll
    for (int f = 0; f < 2; ++f) {
        const int m = wm + f * 16 + (lane >> 2);
        abase[f] = m * 16 + (((m >> 1) & 3) << 2) + (lane & 3);
    }

    float4 la;
    uint4  lb0, lb1;

    float acc[2][8][4];
    #pragma unroll
    for (int f = 0; f < 2; ++f)
        #pragma unroll
        for (int g = 0; g < 8; ++g)
            #pragma unroll
            for (int e = 0; e < 4; ++e) acc[f][g][e] = 0.0f;

    auto ldg = [&](int t) {
        const bool second = (NSRC == 2) && (t >= KT);
        const int s = t & (KT - 1);
        la = *(const float4*)((second ? Ar1 : Ar0) + s * 16);
        if (second) { la.x *= sc; la.y *= sc; la.z *= sc; la.w *= sc; }
        const float* bp = (second ? Bp1 : Bp0) + s * 4096;
        lb0 = ((const uint4*)bp)[0];
        lb1 = ((const uint4*)bp)[1];
    };

    auto sts = [&](int buf) {
        uint4 v;
        v.x = f2tf32(la.x); v.y = f2tf32(la.y);
        v.z = f2tf32(la.z); v.w = f2tf32(la.w);
        *(uint4*)&As[buf][asw] = v;
        *(uint4*)&Bs[buf][tid * 8]     = lb0;
        *(uint4*)&Bs[buf][tid * 8 + 4] = lb1;
    };

    auto compute = [&](int buf) {
        #pragma unroll
        for (int ks = 0; ks < 2; ++ks) {
            uint32_t a[2][4];
            #pragma unroll
            for (int f = 0; f < 2; ++f) {
                const int b0 = abase[f] ^ (ks << 3);
                a[f][0] = As[buf][b0];
                a[f][1] = As[buf][b0 + 128];
                a[f][2] = As[buf][b0 ^ 4];
                a[f][3] = As[buf][(b0 + 128) ^ 4];
            }
            #pragma unroll
            for (int g = 0; g < 8; ++g) {
                const int blk = ((wn >> 3) + g) * 2 + ks;
                uint2 b = *(const uint2*)&Bs[buf][blk * 64 + lane * 2];
                mma_tf32(acc[0][g], a[0], (const uint32_t*)&b);
                mma_tf32(acc[1][g], a[1], (const uint32_t*)&b);
            }
        }
    };

    // ---- pipeline ----
    ldg(0);
    sts(0);
    __syncthreads();
    for (int t = 0; t < TOTAL; ++t) {
        const int buf = t & 1;
        if (t + 1 < TOTAL) ldg(t + 1);
        compute(buf);
        if (t + 1 < TOTAL) {
            sts(buf ^ 1);
            __syncthreads();
        }
    }

    // ---- epilogue: warp tile 32x64, row-major float2 stores ----
    #pragma unroll
    for (int f = 0; f < 2; ++f) {
        #pragma unroll
        for (int g = 0; g < 8; ++g) {
            const int row0 = bm + wm + f * 16 + (lane >> 2);
            const int col  = bn + wn + g * 8 + (lane & 3) * 2;
            float2 v0 = make_float2(acc[f][g][0], acc[f][g][1]);
            float2 v1 = make_float2(acc[f][g][2], acc[f][g][3]);
            if (RELU) {
                v0.x = fmaxf(v0.x, 0.f); v0.y = fmaxf(v0.y, 0.f);
                v1.x = fmaxf(v1.x, 0.f); v1.y = fmaxf(v1.y, 0.f);
            }
            *(float2*)&C[(size_t)row0 * E_ + col]       = v0;
            *(float2*)&C[(size_t)(row0 + 8) * E_ + col] = v1;
        }
    }
}

// ---------------- final concat: out[t] = [h[head], r, h[tail]] --------------
__global__ void final_gather(const float* __restrict__ h,
                             const float* __restrict__ r,
                             const int* __restrict__ head,
                             const int* __restrict__ tail,
                             float* __restrict__ out) {
    const int t = blockIdx.x;
    const int b = t / MT;
    const float4* hh = (const float4*)(h + ((size_t)b * MC + head[t]) * E_);
    const float4* ht = (const float4*)(h + ((size_t)b * MC + tail[t]) * E_);
    const float4* rr = (const float4*)(r + (size_t)t * E_);
    float4* o = (float4*)(out + (size_t)t * 3 * E_);
    const int i = threadIdx.x;
    o[i]       = hh[i];
    o[128 + i] = rr[i];
    o[256 + i] = ht[i];
}

// ---------------- host launch ------------------------------------------------
extern "C" void kernel_launch(void* const* d_in, const int* in_sizes, int n_in,
                              void* d_out, int out_size) {
    const float* concept_table  = (const float*)d_in[0];
    const float* relation_table = (const float*)d_in[1];
    const float* W_s            = (const float*)d_in[2];
    const float* W_n            = (const float*)d_in[3];
    const float* W_r            = (const float*)d_in[4];
    const int*   concept_ids    = (const int*)d_in[5];
    const int*   relation_ids   = (const int*)d_in[6];
    const int*   head_idx       = (const int*)d_in[7];
    const int*   tail_idx       = (const int*)d_in[8];
    const int*   labels         = (const int*)d_in[9];
    float*       out            = (float*)d_out;

    float *h, *h2, *r, *r2, *upd, *wf;
    cudaGetSymbolAddress((void**)&h,   g_h);
    cudaGetSymbolAddress((void**)&h2,  g_h2);
    cudaGetSymbolAddress((void**)&r,   g_r);
    cudaGetSymbolAddress((void**)&r2,  g_r2);
    cudaGetSymbolAddress((void**)&upd, g_upd);
    cudaGetSymbolAddress((void**)&wf,  g_wf);
    float* cnt = upd + (size_t)NROW_H * E_;     // tail of g_upd

    gather_rows<<<NROW_H, 128>>>(concept_table, concept_ids, h);    // 0
    gather_rows<<<NROW_R, 128>>>(relation_table, relation_ids, r);  // 1
    frag_weights<<<6 * MAT / 256, 256>>>(W_s, W_n, W_r, wf);        // 2

    float* hc = h;  float* hn = h2;
    float* rc = r;  float* rn = r2;

    for (int l = 0; l < NHOP; ++l) {
        // one fused memset: upd + cnt                                // 3
        cudaMemsetAsync(upd, 0, sizeof(float) * ((size_t)NROW_H * E_ + NROW_H));

        scatter_upd<<<NROW_R, 128>>>(head_idx, tail_idx, labels, hc, rc, upd, cnt); // 4

        const float* Wsf = wf + (size_t)(0 + l) * MAT;
        const float* Wnf = wf + (size_t)(2 + l) * MAT;
        const float* Wrf = wf + (size_t)(4 + l) * MAT;

        dim3 gh(E_ / 256, NROW_H / 128);            // (2, 256)
        dim3 gr(E_ / 256, NROW_R / 128);            // (2, 512)
        // launch 5 on hop 0 -> ncu captures this GEMM
        gemm_tf32<2, true ><<<gh, 512>>>(hc, Wsf, upd, Wnf, cnt, hn);
        gemm_tf32<1, false><<<gr, 512>>>(rc, Wrf, rc, Wrf, (const float*)nullptr, rn);

        float* tmp;
        tmp = hc; hc = hn; hn = tmp;
        tmp = rc; rc = rn; rn = tmp;
    }

    final_gather<<<NROW_R, 128>>>(hc, rc, head_idx, tail_idx, out);
}

// round 7
// speedup vs baseline: 1.9783x; 1.4500x over previous
#include <cuda_runtime.h>
#include <cuda_fp16.h>
#include <cstdint>
#include <cstring>

// Problem constants (fixed by the dataset)
#define B_   16
#define MC   2048
#define MT   4096
#define E_   512
#define NHOP 2

#define NROW_H (B_ * MC)   // 32768
#define NROW_R (B_ * MT)   // 65536
#define MAT    (E_ * E_)   // 262144

// ---------------- scratch (static device globals; no allocation allowed) ---
__device__ float  g_h  [NROW_H * E_];
__device__ float  g_h2 [NROW_H * E_];
__device__ float  g_upd[NROW_H * E_ + NROW_H];   // cnt lives in the tail
__device__ float  g_r  [NROW_R * E_];
__device__ float  g_r2 [NROW_R * E_];
__device__ __half g_wf [6 * MAT];                // fp16 pre-swizzled weights
                                                 // [Ws0,Ws1,Wn0,Wn1,Wr0,Wr1]

// ---------------- bit-cast helper (no such intrinsic in CUDA) ----------------
__device__ __forceinline__ uint32_t h2u(__half2 v) {
    uint32_t r;
    memcpy(&r, &v, 4);
    return r;
}

// ---------------- mma / ldmatrix helpers -------------------------------------
__device__ __forceinline__ void ldsm4(uint32_t* r, uint32_t addr) {
    asm volatile("ldmatrix.sync.aligned.m8n8.x4.shared.b16 {%0,%1,%2,%3}, [%4];"
                 : "=r"(r[0]), "=r"(r[1]), "=r"(r[2]), "=r"(r[3]) : "r"(addr));
}

__device__ __forceinline__ void mma_fp16(float* c, const uint32_t* a,
                                         uint32_t b0, uint32_t b1) {
    asm volatile(
        "mma.sync.aligned.m16n8k16.row.col.f32.f16.f16.f32 "
        "{%0,%1,%2,%3}, {%4,%5,%6,%7}, {%8,%9}, {%0,%1,%2,%3};\n"
        : "+f"(c[0]), "+f"(c[1]), "+f"(c[2]), "+f"(c[3])
        : "r"(a[0]), "r"(a[1]), "r"(a[2]), "r"(a[3]), "r"(b0), "r"(b1));
}

// ---------------- gather: out[row] = table[ids[row]] ------------------------
__global__ void gather_rows(const float* __restrict__ table,
                            const int* __restrict__ ids,
                            float* __restrict__ out) {
    const int row = blockIdx.x;
    const int id  = ids[row];
    const float4* src = (const float4*)(table + (size_t)id * E_);
    float4*       dst = (float4*)(out + (size_t)row * E_);
    dst[threadIdx.x] = src[threadIdx.x];
}

// ---------------- weight prep: fp32 row-major -> fp16 pre-swizzled tiles ----
// Tile = (panel p: 256 N-rows) x (slice s: 32 K-cols), row-major 64B rows,
// 16B unit u swizzled: u' = u ^ ((n_local>>1)&3).
// dst halfs: mat*MAT + (p*16+s)*8192 + n_local*32 + u'*8 + e
__global__ void prep_weights(const float* __restrict__ Ws,
                             const float* __restrict__ Wn,
                             const float* __restrict__ Wr,
                             __half* __restrict__ dst) {
    const int idx = blockIdx.x * 256 + threadIdx.x;   // one 16B unit each
    const int mat  = idx >> 15;                       // /32768
    const int rem  = idx & 32767;
    const int p    = rem >> 14;
    const int s    = (rem >> 10) & 15;
    const int nl   = (rem >> 2) & 255;
    const int u    = rem & 3;
    const float* src = (mat < 2) ? Ws + (size_t)mat * MAT
                     : (mat < 4) ? Wn + (size_t)(mat - 2) * MAT
                                 : Wr + (size_t)(mat - 4) * MAT;
    const float* sp = src + (size_t)(p * 256 + nl) * E_ + s * 32 + u * 8;
    float4 v0 = ((const float4*)sp)[0];
    float4 v1 = ((const float4*)sp)[1];
    uint4 o;
    o.x = h2u(__floats2half2_rn(v0.x, v0.y));
    o.y = h2u(__floats2half2_rn(v0.z, v0.w));
    o.z = h2u(__floats2half2_rn(v1.x, v1.y));
    o.w = h2u(__floats2half2_rn(v1.z, v1.w));
    const int up = u ^ ((nl >> 1) & 3);
    *(uint4*)(dst + (size_t)mat * MAT + ((p * 16 + s) * 8192) + nl * 32 + up * 8) = o;
}

// ---------------- scatter messages + degree counts (vector red) -------------
__device__ __forceinline__ void red4(float* p, float a, float b, float c, float d) {
    asm volatile("red.global.add.v4.f32 [%0], {%1, %2, %3, %4};"
                 :: "l"(p), "f"(a), "f"(b), "f"(c), "f"(d) : "memory");
}

__global__ void scatter_upd(const int* __restrict__ head,
                            const int* __restrict__ tail,
                            const int* __restrict__ labels,
                            const float* __restrict__ h,
                            const float* __restrict__ r,
                            float* __restrict__ upd,
                            float* __restrict__ cnt) {
    const int t = blockIdx.x;
    if (labels[t] == -1) return;
    const int b  = t / MT;
    const size_t rowh = (size_t)b * MC + head[t];
    const size_t rowt = (size_t)b * MC + tail[t];

    const float4* hh = (const float4*)(h + rowh * E_);
    const float4* ht = (const float4*)(h + rowt * E_);
    const float4* rr = (const float4*)(r + (size_t)t * E_);
    float* ut = upd + rowt * E_;
    float* uh = upd + rowh * E_;

    const int i = threadIdx.x;
    float4 hv = hh[i];
    float4 tv = ht[i];
    float4 rv = rr[i];
    const int o = 4 * i;
    red4(ut + o, hv.x - rv.x, hv.y - rv.y, hv.z - rv.z, hv.w - rv.w);
    red4(uh + o, tv.x - rv.x, tv.y - rv.y, tv.z - rv.z, tv.w - rv.w);
    if (i == 0) {
        atomicAdd(cnt + rowt, 1.0f);
        atomicAdd(cnt + rowh, 1.0f);
    }
}

// ==================== fp16 tensor-core GEMM NT ====================
// C[m,n] = sum_src sum_k A_src[m,k] * W_src[n,k],  K = 512 per source.
// CTA 128x256, BK=32, double-buffered, 512 threads = 16 warps (4x4 grid of
// 32x64 warp tiles). A: fp32 -> fp16 at staging into swizzled row-major smem;
// B: identity copy of pre-swizzled fp16 gmem. Fragments via ldmatrix.x4
// (conflict-free under the (row>>1)&3 unit swizzle). mma.m16n8k16 fp16->fp32.
// Second A source rows scaled by 1/clip(cnt,1) at staging (fused scale_upd).
template<int NSRC, bool RELU>
__global__ __launch_bounds__(512, 1)
void gemm_fp16(const float* __restrict__ A0, const __half* __restrict__ Wf0,
               const float* __restrict__ A1, const __half* __restrict__ Wf1,
               const float* __restrict__ cnt, float* __restrict__ C) {
    constexpr int KT = E_ / 32;                // 16 K-slices per source
    constexpr int TOTAL = NSRC * KT;

    __shared__ __align__(16) char sm[49152];   // As[2]:0,8K  Bs[2]:16K,32K
    const uint32_t sbase = (uint32_t)__cvta_generic_to_shared(sm);

    const int tid  = threadIdx.x;
    const int lane = tid & 31;
    const int wq   = tid >> 5;                 // warp 0..15
    const int wm   = (wq >> 2) * 32;
    const int wn   = (wq & 3) * 64;
    const int bm   = blockIdx.y * 128;
    const int bn   = blockIdx.x * 256;

    // ---- A staging geometry: thread owns (row r, float4 j) and (r+64, j) ----
    const int ar = tid >> 3;                   // 0..63
    const int aj = tid & 7;                    // float4 within 32-float row
    const int adst = ar * 64 + (((aj >> 1) ^ ((ar >> 1) & 3)) << 4) + ((aj & 1) << 3);
    const float* Arow0 = A0 + (size_t)(bm + ar) * E_ + aj * 4;
    const float* Arow1 = (NSRC == 2) ? (A1 + (size_t)(bm + ar) * E_ + aj * 4) : nullptr;
    float sc0 = 1.0f, sc1 = 1.0f;
    if (NSRC == 2) {
        sc0 = 1.0f / fmaxf(cnt[bm + ar], 1.0f);
        sc1 = 1.0f / fmaxf(cnt[bm + ar + 64], 1.0f);
    }

    // ---- B staging: identity copy of 16KB pre-swizzled slice ----
    const __half* Bt0 = Wf0 + (size_t)blockIdx.x * 16 * 8192 + tid * 8;
    const __half* Bt1 = (NSRC == 2) ? (Wf1 + (size_t)blockIdx.x * 16 * 8192 + tid * 8) : nullptr;

    // ---- ldmatrix fragment offsets (within one buffer) ----
    const int mloc  = (lane & 7) + ((lane >> 3) & 1) * 8;
    const int khalf = lane >> 4;
    int aoff[2][2], boff[4][2];
    #pragma unroll
    for (int f = 0; f < 2; ++f) {
        const int row = wm + f * 16 + mloc;
        const int sw  = (row >> 1) & 3;
        #pragma unroll
        for (int kk = 0; kk < 2; ++kk)
            aoff[f][kk] = row * 64 + ((((kk << 1) | khalf) ^ sw) << 4);
    }
    #pragma unroll
    for (int q = 0; q < 4; ++q) {
        const int row = wn + q * 16 + mloc;
        const int sw  = (row >> 1) & 3;
        #pragma unroll
        for (int kk = 0; kk < 2; ++kk)
            boff[q][kk] = row * 64 + ((((kk << 1) | khalf) ^ sw) << 4);
    }

    float4 la0, la1;
    uint4  lb0, lb1;

    float acc[2][8][4];
    #pragma unroll
    for (int f = 0; f < 2; ++f)
        #pragma unroll
        for (int g = 0; g < 8; ++g)
            #pragma unroll
            for (int e = 0; e < 4; ++e) acc[f][g][e] = 0.0f;

    auto ldg = [&](int t) {
        const bool second = (NSRC == 2) && (t >= KT);
        const int s = t & (KT - 1);
        const float* ap = (second ? Arow1 : Arow0) + s * 32;
        la0 = *(const float4*)ap;
        la1 = *(const float4*)(ap + 64 * E_);
        if (second) {
            la0.x *= sc0; la0.y *= sc0; la0.z *= sc0; la0.w *= sc0;
            la1.x *= sc1; la1.y *= sc1; la1.z *= sc1; la1.w *= sc1;
        }
        const __half* bp = (second ? Bt1 : Bt0) + (size_t)s * 8192;
        lb0 = ((const uint4*)bp)[0];
        lb1 = ((const uint4*)(bp + 4096))[0];
    };

    auto sts = [&](int buf) {
        char* ab = sm + buf * 8192;
        uint2 v0, v1;
        v0.x = h2u(__floats2half2_rn(la0.x, la0.y));
        v0.y = h2u(__floats2half2_rn(la0.z, la0.w));
        v1.x = h2u(__floats2half2_rn(la1.x, la1.y));
        v1.y = h2u(__floats2half2_rn(la1.z, la1.w));
        *(uint2*)(ab + adst)            = v0;
        *(uint2*)(ab + adst + 64 * 64)  = v1;   // row+64, same swizzle phase
        char* bb = sm + 16384 + buf * 16384;
        *(uint4*)(bb + tid * 16)        = lb0;
        *(uint4*)(bb + tid * 16 + 8192) = lb1;
    };

    auto compute = [&](int buf) {
        const uint32_t ab = sbase + buf * 8192;
        const uint32_t bb = sbase + 16384 + buf * 16384;
        #pragma unroll
        for (int kk = 0; kk < 2; ++kk) {
            uint32_t a0[4], a1[4];
            ldsm4(a0, ab + aoff[0][kk]);
            ldsm4(a1, ab + aoff[1][kk]);
            #pragma unroll
            for (int q = 0; q < 4; ++q) {
                uint32_t b[4];
                ldsm4(b, bb + boff[q][kk]);
                mma_fp16(acc[0][q * 2 + 0], a0, b[0], b[2]);
                mma_fp16(acc[0][q * 2 + 1], a0, b[1], b[3]);
                mma_fp16(acc[1][q * 2 + 0], a1, b[0], b[2]);
                mma_fp16(acc[1][q * 2 + 1], a1, b[1], b[3]);
            }
        }
    };

    // ---- pipeline ----
    ldg(0);
    sts(0);
    __syncthreads();
    for (int t = 0; t < TOTAL; ++t) {
        const int buf = t & 1;
        if (t + 1 < TOTAL) ldg(t + 1);
        compute(buf);
        if (t + 1 < TOTAL) {
            sts(buf ^ 1);
            __syncthreads();
        }
    }

    // ---- epilogue: warp tile 32x64 ----
    #pragma unroll
    for (int f = 0; f < 2; ++f) {
        #pragma unroll
        for (int g = 0; g < 8; ++g) {
            const int row0 = bm + wm + f * 16 + (lane >> 2);
            const int col  = bn + wn + g * 8 + (lane & 3) * 2;
            float2 v0 = make_float2(acc[f][g][0], acc[f][g][1]);
            float2 v1 = make_float2(acc[f][g][2], acc[f][g][3]);
            if (RELU) {
                v0.x = fmaxf(v0.x, 0.f); v0.y = fmaxf(v0.y, 0.f);
                v1.x = fmaxf(v1.x, 0.f); v1.y = fmaxf(v1.y, 0.f);
            }
            *(float2*)&C[(size_t)row0 * E_ + col]       = v0;
            *(float2*)&C[(size_t)(row0 + 8) * E_ + col] = v1;
        }
    }
}

// ---------------- final concat: out[t] = [h[head], r, h[tail]] --------------
__global__ void final_gather(const float* __restrict__ h,
                             const float* __restrict__ r,
                             const int* __restrict__ head,
                             const int* __restrict__ tail,
                             float* __restrict__ out) {
    const int t = blockIdx.x;
    const int b = t / MT;
    const float4* hh = (const float4*)(h + ((size_t)b * MC + head[t]) * E_);
    const float4* ht = (const float4*)(h + ((size_t)b * MC + tail[t]) * E_);
    const float4* rr = (const float4*)(r + (size_t)t * E_);
    float4* o = (float4*)(out + (size_t)t * 3 * E_);
    const int i = threadIdx.x;
    o[i]       = hh[i];
    o[128 + i] = rr[i];
    o[256 + i] = ht[i];
}

// ---------------- host launch ------------------------------------------------
extern "C" void kernel_launch(void* const* d_in, const int* in_sizes, int n_in,
                              void* d_out, int out_size) {
    const float* concept_table  = (const float*)d_in[0];
    const float* relation_table = (const float*)d_in[1];
    const float* W_s            = (const float*)d_in[2];
    const float* W_n            = (const float*)d_in[3];
    const float* W_r            = (const float*)d_in[4];
    const int*   concept_ids    = (const int*)d_in[5];
    const int*   relation_ids   = (const int*)d_in[6];
    const int*   head_idx       = (const int*)d_in[7];
    const int*   tail_idx       = (const int*)d_in[8];
    const int*   labels         = (const int*)d_in[9];
    float*       out            = (float*)d_out;

    float *h, *h2, *r, *r2, *upd;
    __half* wf;
    cudaGetSymbolAddress((void**)&h,   g_h);
    cudaGetSymbolAddress((void**)&h2,  g_h2);
    cudaGetSymbolAddress((void**)&r,   g_r);
    cudaGetSymbolAddress((void**)&r2,  g_r2);
    cudaGetSymbolAddress((void**)&upd, g_upd);
    cudaGetSymbolAddress((void**)&wf,  g_wf);
    float* cnt = upd + (size_t)NROW_H * E_;     // tail of g_upd

    gather_rows<<<NROW_H, 128>>>(concept_table, concept_ids, h);    // 0
    gather_rows<<<NROW_R, 128>>>(relation_table, relation_ids, r);  // 1
    prep_weights<<<6 * MAT / 8 / 256, 256>>>(W_s, W_n, W_r, wf);    // 2

    float* hc = h;  float* hn = h2;
    float* rc = r;  float* rn = r2;

    for (int l = 0; l < NHOP; ++l) {
        // fused memset: upd + cnt                                   // 3
        cudaMemsetAsync(upd, 0, sizeof(float) * ((size_t)NROW_H * E_ + NROW_H));

        scatter_upd<<<NROW_R, 128>>>(head_idx, tail_idx, labels, hc, rc, upd, cnt); // 4

        const __half* Wsf = wf + (size_t)(0 + l) * MAT;
        const __half* Wnf = wf + (size_t)(2 + l) * MAT;
        const __half* Wrf = wf + (size_t)(4 + l) * MAT;

        dim3 gh(E_ / 256, NROW_H / 128);            // (2, 256)
        dim3 gr(E_ / 256, NROW_R / 128);            // (2, 512)
        // launch 5 on hop 0 -> ncu captures this GEMM
        gemm_fp16<2, true ><<<gh, 512>>>(hc, Wsf, upd, Wnf, cnt, hn);
        gemm_fp16<1, false><<<gr, 512>>>(rc, Wrf, rc, Wrf, (const float*)nullptr, rn);

        float* tmp;
        tmp = hc; hc = hn; hn = tmp;
        tmp = rc; rc = rn; rn = tmp;
    }

    final_gather<<<NROW_R, 128>>>(hc, rc, head_idx, tail_idx, out);
}

// round 8
// speedup vs baseline: 2.5870x; 1.3077x over previous
#include <cuda_runtime.h>
#include <cuda_fp16.h>
#include <cstdint>
#include <cstring>

// Problem constants (fixed by the dataset)
#define B_   16
#define MC   2048
#define MT   4096
#define E_   512
#define NHOP 2

#define NROW_H (B_ * MC)   // 32768
#define NROW_R (B_ * MT)   // 65536
#define MAT    (E_ * E_)   // 262144

// ---------------- scratch (static device globals; no allocation allowed) ---
__device__ __half g_h16[NROW_H * E_];            // h after hop 0 (fp16)
__device__ __half g_r16[NROW_R * E_];            // r after hop 0 (fp16)
__device__ float  g_h2 [NROW_H * E_];            // h after hop 1 (fp32, final)
__device__ float  g_upd[NROW_H * E_ + NROW_H];   // cnt lives in the tail
__device__ __half g_wf [6 * MAT];                // fp16 pre-swizzled weights
                                                 // [Ws0,Ws1,Wn0,Wn1,Wr0,Wr1]

// ---------------- bit-cast helper --------------------------------------------
__device__ __forceinline__ uint32_t h2u(__half2 v) {
    uint32_t r;
    memcpy(&r, &v, 4);
    return r;
}

// ---------------- mma / ldmatrix helpers -------------------------------------
__device__ __forceinline__ void ldsm4(uint32_t* r, uint32_t addr) {
    asm volatile("ldmatrix.sync.aligned.m8n8.x4.shared.b16 {%0,%1,%2,%3}, [%4];"
                 : "=r"(r[0]), "=r"(r[1]), "=r"(r[2]), "=r"(r[3]) : "r"(addr));
}

__device__ __forceinline__ void mma_fp16(float* c, const uint32_t* a,
                                         uint32_t b0, uint32_t b1) {
    asm volatile(
        "mma.sync.aligned.m16n8k16.row.col.f32.f16.f16.f32 "
        "{%0,%1,%2,%3}, {%4,%5,%6,%7}, {%8,%9}, {%0,%1,%2,%3};\n"
        : "+f"(c[0]), "+f"(c[1]), "+f"(c[2]), "+f"(c[3])
        : "r"(a[0]), "r"(a[1]), "r"(a[2]), "r"(a[3]), "r"(b0), "r"(b1));
}

// ---------------- weight prep: fp32 row-major -> fp16 pre-swizzled tiles ----
// Tile = (panel p: 256 N-rows) x (slice s: 32 K-cols), row-major 64B rows,
// 16B unit u swizzled: u' = u ^ ((n_local>>1)&3).
__global__ void prep_weights(const float* __restrict__ Ws,
                             const float* __restrict__ Wn,
                             const float* __restrict__ Wr,
                             __half* __restrict__ dst) {
    const int idx = blockIdx.x * 256 + threadIdx.x;   // one 16B unit each
    const int mat  = idx >> 15;                       // /32768
    const int rem  = idx & 32767;
    const int p    = rem >> 14;
    const int s    = (rem >> 10) & 15;
    const int nl   = (rem >> 2) & 255;
    const int u    = rem & 3;
    const float* src = (mat < 2) ? Ws + (size_t)mat * MAT
                     : (mat < 4) ? Wn + (size_t)(mat - 2) * MAT
                                 : Wr + (size_t)(mat - 4) * MAT;
    const float* sp = src + (size_t)(p * 256 + nl) * E_ + s * 32 + u * 8;
    float4 v0 = ((const float4*)sp)[0];
    float4 v1 = ((const float4*)sp)[1];
    uint4 o;
    o.x = h2u(__floats2half2_rn(v0.x, v0.y));
    o.y = h2u(__floats2half2_rn(v0.z, v0.w));
    o.z = h2u(__floats2half2_rn(v1.x, v1.y));
    o.w = h2u(__floats2half2_rn(v1.z, v1.w));
    const int up = u ^ ((nl >> 1) & 3);
    *(uint4*)(dst + (size_t)mat * MAT + ((p * 16 + s) * 8192) + nl * 32 + up * 8) = o;
}

// ---------------- scatter messages + degree counts (vector red) -------------
// FIRST: h rows come straight from concept_table[concept_ids[...]] (double
// indirection) and r rows from relation_table[relation_ids[t]] (fp32).
// Otherwise: h/r are fp16 intermediates from the previous hop.
__device__ __forceinline__ void red4(float* p, float a, float b, float c, float d) {
    asm volatile("red.global.add.v4.f32 [%0], {%1, %2, %3, %4};"
                 :: "l"(p), "f"(a), "f"(b), "f"(c), "f"(d) : "memory");
}

__device__ __forceinline__ float4 ld_half4(const __half* p, int o) {
    const __half2* q = (const __half2*)(p + o);
    float2 f0 = __half22float2(q[0]);
    float2 f1 = __half22float2(q[1]);
    return make_float4(f0.x, f0.y, f1.x, f1.y);
}

template<bool FIRST>
__global__ void scatter_upd(const int* __restrict__ head,
                            const int* __restrict__ tail,
                            const int* __restrict__ labels,
                            const int* __restrict__ concept_ids,
                            const int* __restrict__ relation_ids,
                            const float* __restrict__ ctab,
                            const float* __restrict__ rtab,
                            const __half* __restrict__ h16,
                            const __half* __restrict__ r16,
                            float* __restrict__ upd,
                            float* __restrict__ cnt) {
    const int t = blockIdx.x;
    if (labels[t] == -1) return;
    const int b  = t / MT;
    const size_t rowh = (size_t)b * MC + head[t];
    const size_t rowt = (size_t)b * MC + tail[t];

    const int i = threadIdx.x;                 // 0..127
    const int o = 4 * i;
    float4 hv, tv, rv;
    if (FIRST) {
        const float* hrow = ctab + (size_t)concept_ids[rowh] * E_;
        const float* trow = ctab + (size_t)concept_ids[rowt] * E_;
        const float* rrow = rtab + (size_t)relation_ids[t] * E_;
        hv = ((const float4*)hrow)[i];
        tv = ((const float4*)trow)[i];
        rv = ((const float4*)rrow)[i];
    } else {
        hv = ld_half4(h16 + rowh * E_, o);
        tv = ld_half4(h16 + rowt * E_, o);
        rv = ld_half4(r16 + (size_t)t * E_, o);
    }
    float* ut = upd + rowt * E_;
    float* uh = upd + rowh * E_;
    red4(ut + o, hv.x - rv.x, hv.y - rv.y, hv.z - rv.z, hv.w - rv.w);
    red4(uh + o, tv.x - rv.x, tv.y - rv.y, tv.z - rv.z, tv.w - rv.w);
    if (i == 0) {
        atomicAdd(cnt + rowt, 1.0f);
        atomicAdd(cnt + rowh, 1.0f);
    }
}

// ==================== fp16 tensor-core GEMM NT ====================
// C[m,n] = sum_src sum_k A_src[m,k] * W_src[n,k],  K = 512 per source.
// CTA 128x256, BK=32, double-buffered, 512 threads = 16 warps (4x4 grid of
// 32x64 warp tiles). Inner loop identical to the proven R7 kernel.
//   A0HALF : A0 is fp16 (direct copy to smem);  else fp32 (convert at staging)
//   ids0   : optional row indirection for A0 (gather fused into GEMM)
//   A1     : always fp32 'upd', scaled by 1/clip(cnt,1) at staging (NSRC==2)
//   CHALF  : epilogue writes fp16 (ld = E_); else fp32 with runtime ldc/coff
template<int NSRC, bool RELU, bool A0HALF, bool CHALF>
__global__ __launch_bounds__(512, 1)
void gemm_fp16(const void* __restrict__ A0v, const int* __restrict__ ids0,
               const __half* __restrict__ Wf0,
               const float* __restrict__ A1, const __half* __restrict__ Wf1,
               const float* __restrict__ cnt,
               void* __restrict__ Cv, int ldc, int coff) {
    constexpr int KT = E_ / 32;                // 16 K-slices per source
    constexpr int TOTAL = NSRC * KT;

    __shared__ __align__(16) char sm[49152];   // As[2]:0,8K  Bs[2]:16K,32K
    const uint32_t sbase = (uint32_t)__cvta_generic_to_shared(sm);

    const int tid  = threadIdx.x;
    const int lane = tid & 31;
    const int wq   = tid >> 5;                 // warp 0..15
    const int wm   = (wq >> 2) * 32;
    const int wn   = (wq & 3) * 64;
    const int bm   = blockIdx.y * 128;
    const int bn   = blockIdx.x * 256;

    // ---- A staging geometry: thread owns (row r, 4-elem chunk j), r and r+64 ----
    const int ar = tid >> 3;                   // 0..63
    const int aj = tid & 7;
    const int adst = ar * 64 + (((aj >> 1) ^ ((ar >> 1) & 3)) << 4) + ((aj & 1) << 3);
    const int gr0 = bm + ar, gr1 = bm + ar + 64;
    const int i0 = ids0 ? ids0[gr0] : gr0;
    const int i1 = ids0 ? ids0[gr1] : gr1;
    const __half* Ah0 = nullptr; const __half* Ah1 = nullptr;
    const float*  Af0 = nullptr; const float*  Af1 = nullptr;
    if (A0HALF) {
        Ah0 = (const __half*)A0v + (size_t)i0 * E_ + aj * 4;
        Ah1 = (const __half*)A0v + (size_t)i1 * E_ + aj * 4;
    } else {
        Af0 = (const float*)A0v + (size_t)i0 * E_ + aj * 4;
        Af1 = (const float*)A0v + (size_t)i1 * E_ + aj * 4;
    }
    const float* Au0 = nullptr; const float* Au1 = nullptr;
    float sc0 = 1.0f, sc1 = 1.0f;
    if (NSRC == 2) {
        Au0 = A1 + (size_t)gr0 * E_ + aj * 4;
        Au1 = A1 + (size_t)gr1 * E_ + aj * 4;
        sc0 = 1.0f / fmaxf(cnt[gr0], 1.0f);
        sc1 = 1.0f / fmaxf(cnt[gr1], 1.0f);
    }

    // ---- B staging: identity copy of 16KB pre-swizzled slice ----
    const __half* Bt0 = Wf0 + (size_t)blockIdx.x * 16 * 8192 + tid * 8;
    const __half* Bt1 = (NSRC == 2) ? (Wf1 + (size_t)blockIdx.x * 16 * 8192 + tid * 8) : nullptr;

    // ---- ldmatrix fragment offsets ----
    const int mloc  = (lane & 7) + ((lane >> 3) & 1) * 8;
    const int khalf = lane >> 4;
    int aoff[2][2], boff[4][2];
    #pragma unroll
    for (int f = 0; f < 2; ++f) {
        const int row = wm + f * 16 + mloc;
        const int sw  = (row >> 1) & 3;
        #pragma unroll
        for (int kk = 0; kk < 2; ++kk)
            aoff[f][kk] = row * 64 + ((((kk << 1) | khalf) ^ sw) << 4);
    }
    #pragma unroll
    for (int q = 0; q < 4; ++q) {
        const int row = wn + q * 16 + mloc;
        const int sw  = (row >> 1) & 3;
        #pragma unroll
        for (int kk = 0; kk < 2; ++kk)
            boff[q][kk] = row * 64 + ((((kk << 1) | khalf) ^ sw) << 4);
    }

    float4 la0, la1;           // fp32 staging (converted at sts)
    uint2  lau0, lau1;         // fp16 staging (direct)
    bool   conv = false;       // does the staged A need conversion?
    uint4  lb0, lb1;

    float acc[2][8][4];
    #pragma unroll
    for (int f = 0; f < 2; ++f)
        #pragma unroll
        for (int g = 0; g < 8; ++g)
            #pragma unroll
            for (int e = 0; e < 4; ++e) acc[f][g][e] = 0.0f;

    auto ldg = [&](int t) {
        const bool sec = (NSRC == 2) && (t >= KT);
        const int s = t & (KT - 1);
        if (sec) {
            la0 = *(const float4*)(Au0 + s * 32);
            la1 = *(const float4*)(Au1 + s * 32);
            la0.x *= sc0; la0.y *= sc0; la0.z *= sc0; la0.w *= sc0;
            la1.x *= sc1; la1.y *= sc1; la1.z *= sc1; la1.w *= sc1;
            conv = true;
        } else if (A0HALF) {
            lau0 = *(const uint2*)(Ah0 + s * 32);
            lau1 = *(const uint2*)(Ah1 + s * 32);
            conv = false;
        } else {
            la0 = *(const float4*)(Af0 + s * 32);
            la1 = *(const float4*)(Af1 + s * 32);
            conv = true;
        }
        const __half* bp = (sec ? Bt1 : Bt0) + (size_t)s * 8192;
        lb0 = ((const uint4*)bp)[0];
        lb1 = ((const uint4*)(bp + 4096))[0];
    };

    auto sts = [&](int buf) {
        char* ab = sm + buf * 8192;
        uint2 v0, v1;
        if (conv) {
            v0.x = h2u(__floats2half2_rn(la0.x, la0.y));
            v0.y = h2u(__floats2half2_rn(la0.z, la0.w));
            v1.x = h2u(__floats2half2_rn(la1.x, la1.y));
            v1.y = h2u(__floats2half2_rn(la1.z, la1.w));
        } else {
            v0 = lau0;
            v1 = lau1;
        }
        *(uint2*)(ab + adst)            = v0;
        *(uint2*)(ab + adst + 64 * 64)  = v1;   // row+64, same swizzle phase
        char* bb = sm + 16384 + buf * 16384;
        *(uint4*)(bb + tid * 16)        = lb0;
        *(uint4*)(bb + tid * 16 + 8192) = lb1;
    };

    auto compute = [&](int buf) {
        const uint32_t ab = sbase + buf * 8192;
        const uint32_t bb = sbase + 16384 + buf * 16384;
        #pragma unroll
        for (int kk = 0; kk < 2; ++kk) {
            uint32_t a0[4], a1[4];
            ldsm4(a0, ab + aoff[0][kk]);
            ldsm4(a1, ab + aoff[1][kk]);
            #pragma unroll
            for (int q = 0; q < 4; ++q) {
                uint32_t b[4];
                ldsm4(b, bb + boff[q][kk]);
                mma_fp16(acc[0][q * 2 + 0], a0, b[0], b[2]);
                mma_fp16(acc[0][q * 2 + 1], a0, b[1], b[3]);
                mma_fp16(acc[1][q * 2 + 0], a1, b[0], b[2]);
                mma_fp16(acc[1][q * 2 + 1], a1, b[1], b[3]);
            }
        }
    };

    // ---- pipeline ----
    ldg(0);
    sts(0);
    __syncthreads();
    for (int t = 0; t < TOTAL; ++t) {
        const int buf = t & 1;
        if (t + 1 < TOTAL) ldg(t + 1);
        compute(buf);
        if (t + 1 < TOTAL) {
            sts(buf ^ 1);
            __syncthreads();
        }
    }

    // ---- epilogue: warp tile 32x64 ----
    #pragma unroll
    for (int f = 0; f < 2; ++f) {
        #pragma unroll
        for (int g = 0; g < 8; ++g) {
            const int row0 = bm + wm + f * 16 + (lane >> 2);
            const int col  = wn + g * 8 + (lane & 3) * 2;
            float2 v0 = make_float2(acc[f][g][0], acc[f][g][1]);
            float2 v1 = make_float2(acc[f][g][2], acc[f][g][3]);
            if (RELU) {
                v0.x = fmaxf(v0.x, 0.f); v0.y = fmaxf(v0.y, 0.f);
                v1.x = fmaxf(v1.x, 0.f); v1.y = fmaxf(v1.y, 0.f);
            }
            if (CHALF) {
                __half* Ch = (__half*)Cv;
                *(uint32_t*)&Ch[(size_t)row0 * E_ + bn + col] =
                    h2u(__floats2half2_rn(v0.x, v0.y));
                *(uint32_t*)&Ch[(size_t)(row0 + 8) * E_ + bn + col] =
                    h2u(__floats2half2_rn(v1.x, v1.y));
            } else {
                float* Cf = (float*)Cv;
                *(float2*)&Cf[(size_t)row0 * ldc + coff + bn + col]       = v0;
                *(float2*)&Cf[(size_t)(row0 + 8) * ldc + coff + bn + col] = v1;
            }
        }
    }
}

// ---------------- final: out[t] = [h2[head], (r written by GEMM), h2[tail]] --
__global__ void final_gather_ht(const float* __restrict__ h2,
                                const int* __restrict__ head,
                                const int* __restrict__ tail,
                                float* __restrict__ out) {
    const int t = blockIdx.x;
    const int b = t / MT;
    const float4* hh = (const float4*)(h2 + ((size_t)b * MC + head[t]) * E_);
    const float4* ht = (const float4*)(h2 + ((size_t)b * MC + tail[t]) * E_);
    float4* o = (float4*)(out + (size_t)t * 3 * E_);
    const int i = threadIdx.x;                 // 0..127
    o[i]       = hh[i];
    o[256 + i] = ht[i];
}

// ---------------- host launch ------------------------------------------------
extern "C" void kernel_launch(void* const* d_in, const int* in_sizes, int n_in,
                              void* d_out, int out_size) {
    const float* concept_table  = (const float*)d_in[0];
    const float* relation_table = (const float*)d_in[1];
    const float* W_s            = (const float*)d_in[2];
    const float* W_n            = (const float*)d_in[3];
    const float* W_r            = (const float*)d_in[4];
    const int*   concept_ids    = (const int*)d_in[5];
    const int*   relation_ids   = (const int*)d_in[6];
    const int*   head_idx       = (const int*)d_in[7];
    const int*   tail_idx       = (const int*)d_in[8];
    const int*   labels         = (const int*)d_in[9];
    float*       out            = (float*)d_out;

    __half *h16, *r16, *wf;
    float *h2, *upd;
    cudaGetSymbolAddress((void**)&h16, g_h16);
    cudaGetSymbolAddress((void**)&r16, g_r16);
    cudaGetSymbolAddress((void**)&h2,  g_h2);
    cudaGetSymbolAddress((void**)&upd, g_upd);
    cudaGetSymbolAddress((void**)&wf,  g_wf);
    float* cnt = upd + (size_t)NROW_H * E_;     // tail of g_upd

    prep_weights<<<6 * MAT / 8 / 256, 256>>>(W_s, W_n, W_r, wf);

    const dim3 gh(E_ / 256, NROW_H / 128);      // (2, 256)
    const dim3 gr(E_ / 256, NROW_R / 128);      // (2, 512)

    // ---------------- hop 0 (inputs read straight from the tables) ----------
    cudaMemsetAsync(upd, 0, sizeof(float) * ((size_t)NROW_H * E_ + NROW_H));
    scatter_upd<true><<<NROW_R, 128>>>(head_idx, tail_idx, labels,
                                       concept_ids, relation_ids,
                                       concept_table, relation_table,
                                       nullptr, nullptr, upd, cnt);
    gemm_fp16<2, true,  false, true><<<gh, 512>>>(
        concept_table, concept_ids, wf + 0 * (size_t)MAT,
        upd, wf + 2 * (size_t)MAT, cnt, h16, E_, 0);
    gemm_fp16<1, false, false, true><<<gr, 512>>>(
        relation_table, relation_ids, wf + 4 * (size_t)MAT,
        nullptr, nullptr, nullptr, r16, E_, 0);

    // ---------------- hop 1 (fp16 intermediates; outputs fp32) --------------
    cudaMemsetAsync(upd, 0, sizeof(float) * ((size_t)NROW_H * E_ + NROW_H));
    scatter_upd<false><<<NROW_R, 128>>>(head_idx, tail_idx, labels,
                                        concept_ids, relation_ids,
                                        nullptr, nullptr,
                                        h16, r16, upd, cnt);
    gemm_fp16<2, true,  true, false><<<gh, 512>>>(
        h16, nullptr, wf + 1 * (size_t)MAT,
        upd, wf + 3 * (size_t)MAT, cnt, h2, E_, 0);
    // r-GEMM writes straight into out[:, 512:1024]
    gemm_fp16<1, false, true, false><<<gr, 512>>>(
        r16, nullptr, wf + 5 * (size_t)MAT,
        nullptr, nullptr, nullptr, out, 3 * E_, E_);

    final_gather_ht<<<NROW_R, 128>>>(h2, head_idx, tail_idx, out);
}

// round 9
// speedup vs baseline: 2.6310x; 1.0170x over previous
#include <cuda_runtime.h>
#include <cuda_fp16.h>
#include <cstdint>
#include <cstring>

// Problem constants (fixed by the dataset)
#define B_   16
#define MC   2048
#define MT   4096
#define E_   512
#define NHOP 2

#define NROW_H (B_ * MC)   // 32768
#define NROW_R (B_ * MT)   // 65536
#define MAT    (E_ * E_)   // 262144

// ---------------- scratch (static device globals; no allocation allowed) ---
__device__ __half g_h16[NROW_H * E_];            // h after hop 0 (fp16)
__device__ __half g_r16[NROW_R * E_];            // r after hop 0 (fp16)
__device__ float  g_h2 [NROW_H * E_];            // h after hop 1 (fp32, final)
__device__ float  g_upd[NROW_H * E_ + NROW_H];   // cnt lives in the tail
__device__ __half g_wf [6 * MAT];                // fp16 pre-swizzled weights
                                                 // [Ws0,Ws1,Wn0,Wn1,Wr0,Wr1]

// ---------------- bit-cast helper --------------------------------------------
__device__ __forceinline__ uint32_t h2u(__half2 v) {
    uint32_t r;
    memcpy(&r, &v, 4);
    return r;
}

// ---------------- mma / ldmatrix helpers -------------------------------------
__device__ __forceinline__ void ldsm4(uint32_t* r, uint32_t addr) {
    asm volatile("ldmatrix.sync.aligned.m8n8.x4.shared.b16 {%0,%1,%2,%3}, [%4];"
                 : "=r"(r[0]), "=r"(r[1]), "=r"(r[2]), "=r"(r[3]) : "r"(addr));
}

__device__ __forceinline__ void mma_fp16(float* c, const uint32_t* a,
                                         uint32_t b0, uint32_t b1) {
    asm volatile(
        "mma.sync.aligned.m16n8k16.row.col.f32.f16.f16.f32 "
        "{%0,%1,%2,%3}, {%4,%5,%6,%7}, {%8,%9}, {%0,%1,%2,%3};\n"
        : "+f"(c[0]), "+f"(c[1]), "+f"(c[2]), "+f"(c[3])
        : "r"(a[0]), "r"(a[1]), "r"(a[2]), "r"(a[3]), "r"(b0), "r"(b1));
}

// ---------------- weight prep: fp32 row-major -> fp16 pre-swizzled tiles ----
// Tile = (panel p: 256 N-rows) x (slice s: 32 K-cols), row-major 64B rows,
// 16B unit u swizzled: u' = u ^ ((n_local>>1)&3).
__global__ void prep_weights(const float* __restrict__ Ws,
                             const float* __restrict__ Wn,
                             const float* __restrict__ Wr,
                             __half* __restrict__ dst) {
    const int idx = blockIdx.x * 256 + threadIdx.x;   // one 16B unit each
    const int mat  = idx >> 15;                       // /32768
    const int rem  = idx & 32767;
    const int p    = rem >> 14;
    const int s    = (rem >> 10) & 15;
    const int nl   = (rem >> 2) & 255;
    const int u    = rem & 3;
    const float* src = (mat < 2) ? Ws + (size_t)mat * MAT
                     : (mat < 4) ? Wn + (size_t)(mat - 2) * MAT
                                 : Wr + (size_t)(mat - 4) * MAT;
    const float* sp = src + (size_t)(p * 256 + nl) * E_ + s * 32 + u * 8;
    float4 v0 = ((const float4*)sp)[0];
    float4 v1 = ((const float4*)sp)[1];
    uint4 o;
    o.x = h2u(__floats2half2_rn(v0.x, v0.y));
    o.y = h2u(__floats2half2_rn(v0.z, v0.w));
    o.z = h2u(__floats2half2_rn(v1.x, v1.y));
    o.w = h2u(__floats2half2_rn(v1.z, v1.w));
    const int up = u ^ ((nl >> 1) & 3);
    *(uint4*)(dst + (size_t)mat * MAT + ((p * 16 + s) * 8192) + nl * 32 + up * 8) = o;
}

// ---------------- scatter messages + degree counts (vector red) -------------
__device__ __forceinline__ void red4(float* p, float a, float b, float c, float d) {
    asm volatile("red.global.add.v4.f32 [%0], {%1, %2, %3, %4};"
                 :: "l"(p), "f"(a), "f"(b), "f"(c), "f"(d) : "memory");
}

__device__ __forceinline__ float4 ld_half4(const __half* p, int o) {
    const __half2* q = (const __half2*)(p + o);
    float2 f0 = __half22float2(q[0]);
    float2 f1 = __half22float2(q[1]);
    return make_float4(f0.x, f0.y, f1.x, f1.y);
}

template<bool FIRST>
__global__ void scatter_upd(const int* __restrict__ head,
                            const int* __restrict__ tail,
                            const int* __restrict__ labels,
                            const int* __restrict__ concept_ids,
                            const int* __restrict__ relation_ids,
                            const float* __restrict__ ctab,
                            const float* __restrict__ rtab,
                            const __half* __restrict__ h16,
                            const __half* __restrict__ r16,
                            float* __restrict__ upd,
                            float* __restrict__ cnt) {
    const int t = blockIdx.x;
    if (labels[t] == -1) return;
    const int b  = t / MT;
    const size_t rowh = (size_t)b * MC + head[t];
    const size_t rowt = (size_t)b * MC + tail[t];

    const int i = threadIdx.x;                 // 0..127
    const int o = 4 * i;
    float4 hv, tv, rv;
    if (FIRST) {
        const float* hrow = ctab + (size_t)concept_ids[rowh] * E_;
        const float* trow = ctab + (size_t)concept_ids[rowt] * E_;
        const float* rrow = rtab + (size_t)relation_ids[t] * E_;
        hv = ((const float4*)hrow)[i];
        tv = ((const float4*)trow)[i];
        rv = ((const float4*)rrow)[i];
    } else {
        hv = ld_half4(h16 + rowh * E_, o);
        tv = ld_half4(h16 + rowt * E_, o);
        rv = ld_half4(r16 + (size_t)t * E_, o);
    }
    float* ut = upd + rowt * E_;
    float* uh = upd + rowh * E_;
    red4(ut + o, hv.x - rv.x, hv.y - rv.y, hv.z - rv.z, hv.w - rv.w);
    red4(uh + o, tv.x - rv.x, tv.y - rv.y, tv.z - rv.z, tv.w - rv.w);
    if (i == 0) {
        atomicAdd(cnt + rowt, 1.0f);
        atomicAdd(cnt + rowh, 1.0f);
    }
}

// ==================== fp16 tensor-core GEMM NT ====================
// C[m,n] = sum_src sum_k A_src[m,k] * W_src[n,k],  K = 512 per source.
// CTA 128x256, BK=32, double-buffered, 256 threads = 8 warps in a 2x4 grid
// of 64x64 warp tiles (ratio 32 mma : 8 ldmatrix.x4 per k16-step).
//   A0HALF : A0 is fp16 (direct copy to smem);  else fp32 (convert at staging)
//   ids0   : optional row indirection for A0 (gather fused into GEMM)
//   A1     : always fp32 'upd', scaled by 1/clip(cnt,1) at staging (NSRC==2)
//   CHALF  : epilogue writes fp16 (ld = E_); else fp32 with runtime ldc/coff
template<int NSRC, bool RELU, bool A0HALF, bool CHALF>
__global__ __launch_bounds__(256, 1)
void gemm_fp16(const void* __restrict__ A0v, const int* __restrict__ ids0,
               const __half* __restrict__ Wf0,
               const float* __restrict__ A1, const __half* __restrict__ Wf1,
               const float* __restrict__ cnt,
               void* __restrict__ Cv, int ldc, int coff) {
    constexpr int KT = E_ / 32;                // 16 K-slices per source
    constexpr int TOTAL = NSRC * KT;

    __shared__ __align__(16) char sm[49152];   // As[2]:0,8K  Bs[2]:16K,32K
    const uint32_t sbase = (uint32_t)__cvta_generic_to_shared(sm);

    const int tid  = threadIdx.x;
    const int lane = tid & 31;
    const int wq   = tid >> 5;                 // warp 0..7
    const int wm   = (wq >> 2) * 64;           // warp row base (2 groups)
    const int wn   = (wq & 3) * 64;            // warp col base (4 groups)
    const int bm   = blockIdx.y * 128;
    const int bn   = blockIdx.x * 256;

    // ---- A staging: thread owns 4-elem chunk aj of rows ar+32*i, i=0..3 ----
    const int ar = tid >> 3;                   // 0..31
    const int aj = tid & 7;
    // swizzle phase of (ar+32*i) equals that of ar for all i
    const int adst0 = ar * 64 + (((aj >> 1) ^ ((ar >> 1) & 3)) << 4) + ((aj & 1) << 3);
    const __half* Ah[4]; const float* Af[4]; const float* Au[4];
    float sc[4];
    #pragma unroll
    for (int i = 0; i < 4; ++i) {
        const int gr = bm + ar + 32 * i;
        const int gi = ids0 ? ids0[gr] : gr;
        if (A0HALF) Ah[i] = (const __half*)A0v + (size_t)gi * E_ + aj * 4;
        else        Af[i] = (const float*)A0v + (size_t)gi * E_ + aj * 4;
        if (NSRC == 2) {
            Au[i] = A1 + (size_t)gr * E_ + aj * 4;
            sc[i] = 1.0f / fmaxf(cnt[gr], 1.0f);
        }
    }

    // ---- B staging: 4 x uint4 of the 16KB pre-swizzled slice ----
    const __half* Bt0 = Wf0 + (size_t)blockIdx.x * 16 * 8192 + tid * 8;
    const __half* Bt1 = (NSRC == 2) ? (Wf1 + (size_t)blockIdx.x * 16 * 8192 + tid * 8) : nullptr;

    // ---- ldmatrix fragment offsets ----
    const int mloc  = (lane & 7) + ((lane >> 3) & 1) * 8;
    const int khalf = lane >> 4;
    int aoff[4][2], boff[4][2];
    #pragma unroll
    for (int f = 0; f < 4; ++f) {
        const int row = wm + f * 16 + mloc;
        const int sw  = (row >> 1) & 3;
        #pragma unroll
        for (int kk = 0; kk < 2; ++kk)
            aoff[f][kk] = row * 64 + ((((kk << 1) | khalf) ^ sw) << 4);
    }
    #pragma unroll
    for (int q = 0; q < 4; ++q) {
        const int row = wn + q * 16 + mloc;
        const int sw  = (row >> 1) & 3;
        #pragma unroll
        for (int kk = 0; kk < 2; ++kk)
            boff[q][kk] = row * 64 + ((((kk << 1) | khalf) ^ sw) << 4);
    }

    float4 la[4];              // fp32 staging (converted at sts)
    uint2  lau[4];             // fp16 staging (direct)
    bool   conv = false;
    uint4  lb[4];

    float acc[4][8][4];
    #pragma unroll
    for (int f = 0; f < 4; ++f)
        #pragma unroll
        for (int g = 0; g < 8; ++g)
            #pragma unroll
            for (int e = 0; e < 4; ++e) acc[f][g][e] = 0.0f;

    auto ldg = [&](int t) {
        const bool sec = (NSRC == 2) && (t >= KT);
        const int s = t & (KT - 1);
        if (sec) {
            #pragma unroll
            for (int i = 0; i < 4; ++i) {
                la[i] = *(const float4*)(Au[i] + s * 32);
                la[i].x *= sc[i]; la[i].y *= sc[i];
                la[i].z *= sc[i]; la[i].w *= sc[i];
            }
            conv = true;
        } else if (A0HALF) {
            #pragma unroll
            for (int i = 0; i < 4; ++i) lau[i] = *(const uint2*)(Ah[i] + s * 32);
            conv = false;
        } else {
            #pragma unroll
            for (int i = 0; i < 4; ++i) la[i] = *(const float4*)(Af[i] + s * 32);
            conv = true;
        }
        const __half* bp = (sec ? Bt1 : Bt0) + (size_t)s * 8192;
        #pragma unroll
        for (int q = 0; q < 4; ++q) lb[q] = *(const uint4*)(bp + q * 2048);
    };

    auto sts = [&](int buf) {
        char* ab = sm + buf * 8192;
        #pragma unroll
        for (int i = 0; i < 4; ++i) {
            uint2 v;
            if (conv) {
                v.x = h2u(__floats2half2_rn(la[i].x, la[i].y));
                v.y = h2u(__floats2half2_rn(la[i].z, la[i].w));
            } else {
                v = lau[i];
            }
            *(uint2*)(ab + adst0 + i * 2048) = v;   // +32 rows = +2048 B
        }
        char* bb = sm + 16384 + buf * 16384;
        #pragma unroll
        for (int q = 0; q < 4; ++q)
            *(uint4*)(bb + tid * 16 + q * 4096) = lb[q];
    };

    auto compute = [&](int buf) {
        const uint32_t ab = sbase + buf * 8192;
        const uint32_t bb = sbase + 16384 + buf * 16384;
        #pragma unroll
        for (int kk = 0; kk < 2; ++kk) {
            uint32_t a[4][4];
            #pragma unroll
            for (int f = 0; f < 4; ++f) ldsm4(a[f], ab + aoff[f][kk]);
            #pragma unroll
            for (int q = 0; q < 4; ++q) {
                uint32_t b[4];
                ldsm4(b, bb + boff[q][kk]);
                #pragma unroll
                for (int f = 0; f < 4; ++f) {
                    mma_fp16(acc[f][q * 2 + 0], a[f], b[0], b[2]);
                    mma_fp16(acc[f][q * 2 + 1], a[f], b[1], b[3]);
                }
            }
        }
    };

    // ---- pipeline ----
    ldg(0);
    sts(0);
    __syncthreads();
    for (int t = 0; t < TOTAL; ++t) {
        const int buf = t & 1;
        if (t + 1 < TOTAL) ldg(t + 1);
        compute(buf);
        if (t + 1 < TOTAL) {
            sts(buf ^ 1);
            __syncthreads();
        }
    }

    // ---- epilogue: warp tile 64x64 ----
    #pragma unroll
    for (int f = 0; f < 4; ++f) {
        #pragma unroll
        for (int g = 0; g < 8; ++g) {
            const int row0 = bm + wm + f * 16 + (lane >> 2);
            const int col  = wn + g * 8 + (lane & 3) * 2;
            float2 v0 = make_float2(acc[f][g][0], acc[f][g][1]);
            float2 v1 = make_float2(acc[f][g][2], acc[f][g][3]);
            if (RELU) {
                v0.x = fmaxf(v0.x, 0.f); v0.y = fmaxf(v0.y, 0.f);
                v1.x = fmaxf(v1.x, 0.f); v1.y = fmaxf(v1.y, 0.f);
            }
            if (CHALF) {
                __half* Ch = (__half*)Cv;
                *(uint32_t*)&Ch[(size_t)row0 * E_ + bn + col] =
                    h2u(__floats2half2_rn(v0.x, v0.y));
                *(uint32_t*)&Ch[(size_t)(row0 + 8) * E_ + bn + col] =
                    h2u(__floats2half2_rn(v1.x, v1.y));
            } else {
                float* Cf = (float*)Cv;
                *(float2*)&Cf[(size_t)row0 * ldc + coff + bn + col]       = v0;
                *(float2*)&Cf[(size_t)(row0 + 8) * ldc + coff + bn + col] = v1;
            }
        }
    }
}

// ---------------- final: out[t] = [h2[head], (r written by GEMM), h2[tail]] --
__global__ void final_gather_ht(const float* __restrict__ h2,
                                const int* __restrict__ head,
                                const int* __restrict__ tail,
                                float* __restrict__ out) {
    const int t = blockIdx.x;
    const int b = t / MT;
    const float4* hh = (const float4*)(h2 + ((size_t)b * MC + head[t]) * E_);
    const float4* ht = (const float4*)(h2 + ((size_t)b * MC + tail[t]) * E_);
    float4* o = (float4*)(out + (size_t)t * 3 * E_);
    const int i = threadIdx.x;                 // 0..127
    o[i]       = hh[i];
    o[256 + i] = ht[i];
}

// ---------------- host launch ------------------------------------------------
extern "C" void kernel_launch(void* const* d_in, const int* in_sizes, int n_in,
                              void* d_out, int out_size) {
    const float* concept_table  = (const float*)d_in[0];
    const float* relation_table = (const float*)d_in[1];
    const float* W_s            = (const float*)d_in[2];
    const float* W_n            = (const float*)d_in[3];
    const float* W_r            = (const float*)d_in[4];
    const int*   concept_ids    = (const int*)d_in[5];
    const int*   relation_ids   = (const int*)d_in[6];
    const int*   head_idx       = (const int*)d_in[7];
    const int*   tail_idx       = (const int*)d_in[8];
    const int*   labels         = (const int*)d_in[9];
    float*       out            = (float*)d_out;

    __half *h16, *r16, *wf;
    float *h2, *upd;
    cudaGetSymbolAddress((void**)&h16, g_h16);
    cudaGetSymbolAddress((void**)&r16, g_r16);
    cudaGetSymbolAddress((void**)&h2,  g_h2);
    cudaGetSymbolAddress((void**)&upd, g_upd);
    cudaGetSymbolAddress((void**)&wf,  g_wf);
    float* cnt = upd + (size_t)NROW_H * E_;     // tail of g_upd

    prep_weights<<<6 * MAT / 8 / 256, 256>>>(W_s, W_n, W_r, wf);

    const dim3 gh(E_ / 256, NROW_H / 128);      // (2, 256)
    const dim3 gr(E_ / 256, NROW_R / 128);      // (2, 512)

    // ---------------- hop 0 (inputs read straight from the tables) ----------
    cudaMemsetAsync(upd, 0, sizeof(float) * ((size_t)NROW_H * E_ + NROW_H));
    scatter_upd<true><<<NROW_R, 128>>>(head_idx, tail_idx, labels,
                                       concept_ids, relation_ids,
                                       concept_table, relation_table,
                                       nullptr, nullptr, upd, cnt);
    gemm_fp16<2, true,  false, true><<<gh, 256>>>(
        concept_table, concept_ids, wf + 0 * (size_t)MAT,
        upd, wf + 2 * (size_t)MAT, cnt, h16, E_, 0);
    gemm_fp16<1, false, false, true><<<gr, 256>>>(
        relation_table, relation_ids, wf + 4 * (size_t)MAT,
        nullptr, nullptr, nullptr, r16, E_, 0);

    // ---------------- hop 1 (fp16 intermediates; outputs fp32) --------------
    cudaMemsetAsync(upd, 0, sizeof(float) * ((size_t)NROW_H * E_ + NROW_H));
    scatter_upd<false><<<NROW_R, 128>>>(head_idx, tail_idx, labels,
                                        concept_ids, relation_ids,
                                        nullptr, nullptr,
                                        h16, r16, upd, cnt);
    gemm_fp16<2, true,  true, false><<<gh, 256>>>(
        h16, nullptr, wf + 1 * (size_t)MAT,
        upd, wf + 3 * (size_t)MAT, cnt, h2, E_, 0);
    // r-GEMM writes straight into out[:, 512:1024]
    gemm_fp16<1, false, true, false><<<gr, 256>>>(
        r16, nullptr, wf + 5 * (size_t)MAT,
        nullptr, nullptr, nullptr, out, 3 * E_, E_);

    final_gather_ht<<<NROW_R, 128>>>(h2, head_idx, tail_idx, out);
}

// round 10
// speedup vs baseline: 2.7199x; 1.0338x over previous
#include <cuda_runtime.h>
#include <cuda_fp16.h>
#include <cstdint>
#include <cstring>

// Problem constants (fixed by the dataset)
#define B_   16
#define MC   2048
#define MT   4096
#define E_   512
#define NHOP 2

#define NROW_H (B_ * MC)   // 32768
#define NROW_R (B_ * MT)   // 65536
#define MAT    (E_ * E_)   // 262144

// ---------------- scratch (static device globals; no allocation allowed) ---
__device__ __half g_h16[NROW_H * E_];            // h after hop 0 (fp16)
__device__ __half g_r16[NROW_R * E_];            // r after hop 0 (fp16)
__device__ __half g_h2h[NROW_H * E_];            // h after hop 1 (fp16)
__device__ float  g_upd[NROW_H * E_ + NROW_H];   // cnt lives in the tail
__device__ __half g_wf [6 * MAT];                // fp16 pre-swizzled weights
                                                 // [Ws0,Ws1,Wn0,Wn1,Wr0,Wr1]

// ---------------- bit-cast helper --------------------------------------------
__device__ __forceinline__ uint32_t h2u(__half2 v) {
    uint32_t r;
    memcpy(&r, &v, 4);
    return r;
}

// ---------------- mma / ldmatrix helpers -------------------------------------
__device__ __forceinline__ void ldsm4(uint32_t* r, uint32_t addr) {
    asm volatile("ldmatrix.sync.aligned.m8n8.x4.shared.b16 {%0,%1,%2,%3}, [%4];"
                 : "=r"(r[0]), "=r"(r[1]), "=r"(r[2]), "=r"(r[3]) : "r"(addr));
}

__device__ __forceinline__ void mma_fp16(float* c, const uint32_t* a,
                                         uint32_t b0, uint32_t b1) {
    asm volatile(
        "mma.sync.aligned.m16n8k16.row.col.f32.f16.f16.f32 "
        "{%0,%1,%2,%3}, {%4,%5,%6,%7}, {%8,%9}, {%0,%1,%2,%3};\n"
        : "+f"(c[0]), "+f"(c[1]), "+f"(c[2]), "+f"(c[3])
        : "r"(a[0]), "r"(a[1]), "r"(a[2]), "r"(a[3]), "r"(b0), "r"(b1));
}

// ---------------- weight prep: fp32 row-major -> fp16 pre-swizzled tiles ----
__global__ void prep_weights(const float* __restrict__ Ws,
                             const float* __restrict__ Wn,
                             const float* __restrict__ Wr,
                             __half* __restrict__ dst) {
    const int idx = blockIdx.x * 256 + threadIdx.x;   // one 16B unit each
    const int mat  = idx >> 15;                       // /32768
    const int rem  = idx & 32767;
    const int p    = rem >> 14;
    const int s    = (rem >> 10) & 15;
    const int nl   = (rem >> 2) & 255;
    const int u    = rem & 3;
    const float* src = (mat < 2) ? Ws + (size_t)mat * MAT
                     : (mat < 4) ? Wn + (size_t)(mat - 2) * MAT
                                 : Wr + (size_t)(mat - 4) * MAT;
    const float* sp = src + (size_t)(p * 256 + nl) * E_ + s * 32 + u * 8;
    float4 v0 = ((const float4*)sp)[0];
    float4 v1 = ((const float4*)sp)[1];
    uint4 o;
    o.x = h2u(__floats2half2_rn(v0.x, v0.y));
    o.y = h2u(__floats2half2_rn(v0.z, v0.w));
    o.z = h2u(__floats2half2_rn(v1.x, v1.y));
    o.w = h2u(__floats2half2_rn(v1.z, v1.w));
    const int up = u ^ ((nl >> 1) & 3);
    *(uint4*)(dst + (size_t)mat * MAT + ((p * 16 + s) * 8192) + nl * 32 + up * 8) = o;
}

// ---------------- scatter messages + degree counts (vector red) -------------
__device__ __forceinline__ void red4(float* p, float a, float b, float c, float d) {
    asm volatile("red.global.add.v4.f32 [%0], {%1, %2, %3, %4};"
                 :: "l"(p), "f"(a), "f"(b), "f"(c), "f"(d) : "memory");
}

__device__ __forceinline__ float4 ld_half4(const __half* p, int o) {
    const __half2* q = (const __half2*)(p + o);
    float2 f0 = __half22float2(q[0]);
    float2 f1 = __half22float2(q[1]);
    return make_float4(f0.x, f0.y, f1.x, f1.y);
}

template<bool FIRST>
__global__ void scatter_upd(const int* __restrict__ head,
                            const int* __restrict__ tail,
                            const int* __restrict__ labels,
                            const int* __restrict__ concept_ids,
                            const int* __restrict__ relation_ids,
                            const float* __restrict__ ctab,
                            const float* __restrict__ rtab,
                            const __half* __restrict__ h16,
                            const __half* __restrict__ r16,
                            float* __restrict__ upd,
                            float* __restrict__ cnt) {
    const int t = blockIdx.x;
    if (labels[t] == -1) return;
    const int b  = t / MT;
    const size_t rowh = (size_t)b * MC + head[t];
    const size_t rowt = (size_t)b * MC + tail[t];

    const int i = threadIdx.x;                 // 0..127
    const int o = 4 * i;
    float4 hv, tv, rv;
    if (FIRST) {
        const float* hrow = ctab + (size_t)concept_ids[rowh] * E_;
        const float* trow = ctab + (size_t)concept_ids[rowt] * E_;
        const float* rrow = rtab + (size_t)relation_ids[t] * E_;
        hv = ((const float4*)hrow)[i];
        tv = ((const float4*)trow)[i];
        rv = ((const float4*)rrow)[i];
    } else {
        hv = ld_half4(h16 + rowh * E_, o);
        tv = ld_half4(h16 + rowt * E_, o);
        rv = ld_half4(r16 + (size_t)t * E_, o);
    }
    float* ut = upd + rowt * E_;
    float* uh = upd + rowh * E_;
    red4(ut + o, hv.x - rv.x, hv.y - rv.y, hv.z - rv.z, hv.w - rv.w);
    red4(uh + o, tv.x - rv.x, tv.y - rv.y, tv.z - rv.z, tv.w - rv.w);
    if (i == 0) {
        atomicAdd(cnt + rowt, 1.0f);
        atomicAdd(cnt + rowh, 1.0f);
    }
}

// ==================== fp16 tensor-core GEMM NT (proven R9 core) ==============
// CTA 128x256, BK=32, double-buffered, 256 threads = 8 warps, 64x64 warp tiles.
template<int NSRC, bool RELU, bool A0HALF, bool CHALF>
__global__ __launch_bounds__(256, 1)
void gemm_fp16(const void* __restrict__ A0v, const int* __restrict__ ids0,
               const __half* __restrict__ Wf0,
               const float* __restrict__ A1, const __half* __restrict__ Wf1,
               const float* __restrict__ cnt,
               void* __restrict__ Cv, int ldc, int coff) {
    constexpr int KT = E_ / 32;                // 16 K-slices per source
    constexpr int TOTAL = NSRC * KT;

    __shared__ __align__(16) char sm[49152];   // As[2]:0,8K  Bs[2]:16K,32K
    const uint32_t sbase = (uint32_t)__cvta_generic_to_shared(sm);

    const int tid  = threadIdx.x;
    const int lane = tid & 31;
    const int wq   = tid >> 5;                 // warp 0..7
    const int wm   = (wq >> 2) * 64;
    const int wn   = (wq & 3) * 64;
    const int bm   = blockIdx.y * 128;
    const int bn   = blockIdx.x * 256;

    // ---- A staging: thread owns 4-elem chunk aj of rows ar+32*i, i=0..3 ----
    const int ar = tid >> 3;                   // 0..31
    const int aj = tid & 7;
    const int adst0 = ar * 64 + (((aj >> 1) ^ ((ar >> 1) & 3)) << 4) + ((aj & 1) << 3);
    const __half* Ah[4]; const float* Af[4]; const float* Au[4];
    float sc[4];
    #pragma unroll
    for (int i = 0; i < 4; ++i) {
        const int gr = bm + ar + 32 * i;
        const int gi = ids0 ? ids0[gr] : gr;
        if (A0HALF) Ah[i] = (const __half*)A0v + (size_t)gi * E_ + aj * 4;
        else        Af[i] = (const float*)A0v + (size_t)gi * E_ + aj * 4;
        if (NSRC == 2) {
            Au[i] = A1 + (size_t)gr * E_ + aj * 4;
            sc[i] = 1.0f / fmaxf(cnt[gr], 1.0f);
        }
    }

    // ---- B staging: 4 x uint4 of the 16KB pre-swizzled slice ----
    const __half* Bt0 = Wf0 + (size_t)blockIdx.x * 16 * 8192 + tid * 8;
    const __half* Bt1 = (NSRC == 2) ? (Wf1 + (size_t)blockIdx.x * 16 * 8192 + tid * 8) : nullptr;

    // ---- ldmatrix fragment offsets ----
    const int mloc  = (lane & 7) + ((lane >> 3) & 1) * 8;
    const int khalf = lane >> 4;
    int aoff[4][2], boff[4][2];
    #pragma unroll
    for (int f = 0; f < 4; ++f) {
        const int row = wm + f * 16 + mloc;
        const int sw  = (row >> 1) & 3;
        #pragma unroll
        for (int kk = 0; kk < 2; ++kk)
            aoff[f][kk] = row * 64 + ((((kk << 1) | khalf) ^ sw) << 4);
    }
    #pragma unroll
    for (int q = 0; q < 4; ++q) {
        const int row = wn + q * 16 + mloc;
        const int sw  = (row >> 1) & 3;
        #pragma unroll
        for (int kk = 0; kk < 2; ++kk)
            boff[q][kk] = row * 64 + ((((kk << 1) | khalf) ^ sw) << 4);
    }

    float4 la[4];
    uint2  lau[4];
    bool   conv = false;
    uint4  lb[4];

    float acc[4][8][4];
    #pragma unroll
    for (int f = 0; f < 4; ++f)
        #pragma unroll
        for (int g = 0; g < 8; ++g)
            #pragma unroll
            for (int e = 0; e < 4; ++e) acc[f][g][e] = 0.0f;

    auto ldg = [&](int t) {
        const bool sec = (NSRC == 2) && (t >= KT);
        const int s = t & (KT - 1);
        if (sec) {
            #pragma unroll
            for (int i = 0; i < 4; ++i) {
                la[i] = *(const float4*)(Au[i] + s * 32);
                la[i].x *= sc[i]; la[i].y *= sc[i];
                la[i].z *= sc[i]; la[i].w *= sc[i];
            }
            conv = true;
        } else if (A0HALF) {
            #pragma unroll
            for (int i = 0; i < 4; ++i) lau[i] = *(const uint2*)(Ah[i] + s * 32);
            conv = false;
        } else {
            #pragma unroll
            for (int i = 0; i < 4; ++i) la[i] = *(const float4*)(Af[i] + s * 32);
            conv = true;
        }
        const __half* bp = (sec ? Bt1 : Bt0) + (size_t)s * 8192;
        #pragma unroll
        for (int q = 0; q < 4; ++q) lb[q] = *(const uint4*)(bp + q * 2048);
    };

    auto sts = [&](int buf) {
        char* ab = sm + buf * 8192;
        #pragma unroll
        for (int i = 0; i < 4; ++i) {
            uint2 v;
            if (conv) {
                v.x = h2u(__floats2half2_rn(la[i].x, la[i].y));
                v.y = h2u(__floats2half2_rn(la[i].z, la[i].w));
            } else {
                v = lau[i];
            }
            *(uint2*)(ab + adst0 + i * 2048) = v;   // +32 rows = +2048 B
        }
        char* bb = sm + 16384 + buf * 16384;
        #pragma unroll
        for (int q = 0; q < 4; ++q)
            *(uint4*)(bb + tid * 16 + q * 4096) = lb[q];
    };

    auto compute = [&](int buf) {
        const uint32_t ab = sbase + buf * 8192;
        const uint32_t bb = sbase + 16384 + buf * 16384;
        #pragma unroll
        for (int kk = 0; kk < 2; ++kk) {
            uint32_t a[4][4];
            #pragma unroll
            for (int f = 0; f < 4; ++f) ldsm4(a[f], ab + aoff[f][kk]);
            #pragma unroll
            for (int q = 0; q < 4; ++q) {
                uint32_t b[4];
                ldsm4(b, bb + boff[q][kk]);
                #pragma unroll
                for (int f = 0; f < 4; ++f) {
                    mma_fp16(acc[f][q * 2 + 0], a[f], b[0], b[2]);
                    mma_fp16(acc[f][q * 2 + 1], a[f], b[1], b[3]);
                }
            }
        }
    };

    // ---- pipeline ----
    ldg(0);
    sts(0);
    __syncthreads();
    for (int t = 0; t < TOTAL; ++t) {
        const int buf = t & 1;
        if (t + 1 < TOTAL) ldg(t + 1);
        compute(buf);
        if (t + 1 < TOTAL) {
            sts(buf ^ 1);
            __syncthreads();
        }
    }

    // ---- epilogue: warp tile 64x64 ----
    #pragma unroll
    for (int f = 0; f < 4; ++f) {
        #pragma unroll
        for (int g = 0; g < 8; ++g) {
            const int row0 = bm + wm + f * 16 + (lane >> 2);
            const int col  = wn + g * 8 + (lane & 3) * 2;
            float2 v0 = make_float2(acc[f][g][0], acc[f][g][1]);
            float2 v1 = make_float2(acc[f][g][2], acc[f][g][3]);
            if (RELU) {
                v0.x = fmaxf(v0.x, 0.f); v0.y = fmaxf(v0.y, 0.f);
                v1.x = fmaxf(v1.x, 0.f); v1.y = fmaxf(v1.y, 0.f);
            }
            if (CHALF) {
                __half* Ch = (__half*)Cv;
                *(uint32_t*)&Ch[(size_t)row0 * E_ + bn + col] =
                    h2u(__floats2half2_rn(v0.x, v0.y));
                *(uint32_t*)&Ch[(size_t)(row0 + 8) * E_ + bn + col] =
                    h2u(__floats2half2_rn(v1.x, v1.y));
            } else {
                float* Cf = (float*)Cv;
                *(float2*)&Cf[(size_t)row0 * ldc + coff + bn + col]       = v0;
                *(float2*)&Cf[(size_t)(row0 + 8) * ldc + coff + bn + col] = v1;
            }
        }
    }
}

// ---------------- final: out[t] = [h2[head], (r written by GEMM), h2[tail]] --
__global__ void final_gather_ht(const __half* __restrict__ h2,
                                const int* __restrict__ head,
                                const int* __restrict__ tail,
                                float* __restrict__ out) {
    const int t = blockIdx.x;
    const int b = t / MT;
    const __half* hh = h2 + ((size_t)b * MC + head[t]) * E_;
    const __half* ht = h2 + ((size_t)b * MC + tail[t]) * E_;
    float4* o = (float4*)(out + (size_t)t * 3 * E_);
    const int i = threadIdx.x;                 // 0..127
    const int off = 4 * i;
    o[i]       = ld_half4(hh, off);
    o[256 + i] = ld_half4(ht, off);
}

// ---------------- host launch ------------------------------------------------
extern "C" void kernel_launch(void* const* d_in, const int* in_sizes, int n_in,
                              void* d_out, int out_size) {
    const float* concept_table  = (const float*)d_in[0];
    const float* relation_table = (const float*)d_in[1];
    const float* W_s            = (const float*)d_in[2];
    const float* W_n            = (const float*)d_in[3];
    const float* W_r            = (const float*)d_in[4];
    const int*   concept_ids    = (const int*)d_in[5];
    const int*   relation_ids   = (const int*)d_in[6];
    const int*   head_idx       = (const int*)d_in[7];
    const int*   tail_idx       = (const int*)d_in[8];
    const int*   labels         = (const int*)d_in[9];
    float*       out            = (float*)d_out;

    __half *h16, *r16, *h2h, *wf;
    float *upd;
    cudaGetSymbolAddress((void**)&h16, g_h16);
    cudaGetSymbolAddress((void**)&r16, g_r16);
    cudaGetSymbolAddress((void**)&h2h, g_h2h);
    cudaGetSymbolAddress((void**)&upd, g_upd);
    cudaGetSymbolAddress((void**)&wf,  g_wf);
    float* cnt = upd + (size_t)NROW_H * E_;     // tail of g_upd

    // fork-join scaffolding: r-chain runs on a side stream, event-linked so
    // both branches are captured into (or executed as) one dependency graph.
    cudaStream_t s2;
    cudaStreamCreateWithFlags(&s2, cudaStreamNonBlocking);
    cudaEvent_t eFork0, eJoin0, eFork1, eJoin1;
    cudaEventCreateWithFlags(&eFork0, cudaEventDisableTiming);
    cudaEventCreateWithFlags(&eJoin0, cudaEventDisableTiming);
    cudaEventCreateWithFlags(&eFork1, cudaEventDisableTiming);
    cudaEventCreateWithFlags(&eJoin1, cudaEventDisableTiming);

    const dim3 gh(E_ / 256, NROW_H / 128);      // (2, 256)
    const dim3 gr(E_ / 256, NROW_R / 128);      // (2, 512)

    prep_weights<<<6 * MAT / 8 / 256, 256>>>(W_s, W_n, W_r, wf);
    cudaEventRecord(eFork0, 0);

    // ---- side stream: hop-0 r-GEMM (tables -> r16) --------------------------
    cudaStreamWaitEvent(s2, eFork0, 0);
    gemm_fp16<1, false, false, true><<<gr, 256, 0, s2>>>(
        relation_table, relation_ids, wf + 4 * (size_t)MAT,
        nullptr, nullptr, nullptr, r16, E_, 0);
    cudaEventRecord(eJoin0, s2);

    // ---- main stream: hop-0 h-chain -----------------------------------------
    cudaMemsetAsync(upd, 0, sizeof(float) * ((size_t)NROW_H * E_ + NROW_H));
    scatter_upd<true><<<NROW_R, 128>>>(head_idx, tail_idx, labels,
                                       concept_ids, relation_ids,
                                       concept_table, relation_table,
                                       nullptr, nullptr, upd, cnt);
    gemm_fp16<2, true, false, true><<<gh, 256>>>(
        concept_table, concept_ids, wf + 0 * (size_t)MAT,
        upd, wf + 2 * (size_t)MAT, cnt, h16, E_, 0);

    // join: scatter1 needs r16 from the side stream
    cudaStreamWaitEvent(0, eJoin0, 0);

    // ---- hop 1 ---------------------------------------------------------------
    cudaMemsetAsync(upd, 0, sizeof(float) * ((size_t)NROW_H * E_ + NROW_H));
    scatter_upd<false><<<NROW_R, 128>>>(head_idx, tail_idx, labels,
                                        concept_ids, relation_ids,
                                        nullptr, nullptr,
                                        h16, r16, upd, cnt);
    cudaEventRecord(eFork1, 0);

    // side stream: hop-1 r-GEMM writes straight into out[:, 512:1024]
    cudaStreamWaitEvent(s2, eFork1, 0);
    gemm_fp16<1, false, true, false><<<gr, 256, 0, s2>>>(
        r16, nullptr, wf + 5 * (size_t)MAT,
        nullptr, nullptr, nullptr, out, 3 * E_, E_);
    cudaEventRecord(eJoin1, s2);

    // main stream: hop-1 h-GEMM (fp16 epilogue) + final gather
    gemm_fp16<2, true, true, true><<<gh, 256>>>(
        h16, nullptr, wf + 1 * (size_t)MAT,
        upd, wf + 3 * (size_t)MAT, cnt, h2h, E_, 0);
    final_gather_ht<<<NROW_R, 128>>>(h2h, head_idx, tail_idx, out);

    // join: downstream consumers of out must also see the side-stream r-GEMM
    cudaStreamWaitEvent(0, eJoin1, 0);
}

// round 11
// speedup vs baseline: 2.7679x; 1.0176x over previous
#include <cuda_runtime.h>
#include <cuda_fp16.h>
#include <cstdint>
#include <cstring>

// Problem constants (fixed by the dataset)
#define B_    16
#define MC    2048
#define MT    4096
#define E_    512
#define VOCAB 32000
#define NREL  69

#define NROW_H (B_ * MC)   // 32768
#define NROW_R (B_ * MT)   // 65536
#define MAT    (E_ * E_)   // 262144

// ---------------- scratch (static device globals; no allocation allowed) ---
__device__ __half g_ct16[VOCAB * E_];            // fp16 concept table
__device__ __half g_rt16[NREL * E_];             // fp16 relation table
__device__ __half g_h16[NROW_H * E_];            // h after hop 0 (fp16)
__device__ __half g_r16[NROW_R * E_];            // r after hop 0 (fp16)
__device__ __half g_h2h[NROW_H * E_];            // h after hop 1 (fp16)
__device__ float  g_upd0[NROW_H * E_ + NROW_H];  // hop-0 upd (+cnt tail)
__device__ float  g_upd1[NROW_H * E_ + NROW_H];  // hop-1 upd (+cnt tail)
__device__ __half g_wf [6 * MAT];                // fp16 pre-swizzled weights
                                                 // [Ws0,Ws1,Wn0,Wn1,Wr0,Wr1]

// ---------------- bit-cast helper --------------------------------------------
__device__ __forceinline__ uint32_t h2u(__half2 v) {
    uint32_t r;
    memcpy(&r, &v, 4);
    return r;
}

// ---------------- mma / ldmatrix helpers -------------------------------------
__device__ __forceinline__ void ldsm4(uint32_t* r, uint32_t addr) {
    asm volatile("ldmatrix.sync.aligned.m8n8.x4.shared.b16 {%0,%1,%2,%3}, [%4];"
                 : "=r"(r[0]), "=r"(r[1]), "=r"(r[2]), "=r"(r[3]) : "r"(addr));
}

__device__ __forceinline__ void mma_fp16(float* c, const uint32_t* a,
                                         uint32_t b0, uint32_t b1) {
    asm volatile(
        "mma.sync.aligned.m16n8k16.row.col.f32.f16.f16.f32 "
        "{%0,%1,%2,%3}, {%4,%5,%6,%7}, {%8,%9}, {%0,%1,%2,%3};\n"
        : "+f"(c[0]), "+f"(c[1]), "+f"(c[2]), "+f"(c[3])
        : "r"(a[0]), "r"(a[1]), "r"(a[2]), "r"(a[3]), "r"(b0), "r"(b1));
}

// ---------------- fp32 -> fp16 table conversion ------------------------------
__global__ void to_half(const float* __restrict__ src, __half* __restrict__ dst,
                        int n8) {
    const int i = blockIdx.x * 256 + threadIdx.x;   // one 8-elem chunk each
    if (i >= n8) return;
    float4 a = ((const float4*)src)[2 * i];
    float4 b = ((const float4*)src)[2 * i + 1];
    uint4 o;
    o.x = h2u(__floats2half2_rn(a.x, a.y));
    o.y = h2u(__floats2half2_rn(a.z, a.w));
    o.z = h2u(__floats2half2_rn(b.x, b.y));
    o.w = h2u(__floats2half2_rn(b.z, b.w));
    ((uint4*)dst)[i] = o;
}

// ---------------- weight prep: fp32 row-major -> fp16 pre-swizzled tiles ----
__global__ void prep_weights(const float* __restrict__ Ws,
                             const float* __restrict__ Wn,
                             const float* __restrict__ Wr,
                             __half* __restrict__ dst) {
    const int idx = blockIdx.x * 256 + threadIdx.x;   // one 16B unit each
    const int mat  = idx >> 15;                       // /32768
    const int rem  = idx & 32767;
    const int p    = rem >> 14;
    const int s    = (rem >> 10) & 15;
    const int nl   = (rem >> 2) & 255;
    const int u    = rem & 3;
    const float* src = (mat < 2) ? Ws + (size_t)mat * MAT
                     : (mat < 4) ? Wn + (size_t)(mat - 2) * MAT
                                 : Wr + (size_t)(mat - 4) * MAT;
    const float* sp = src + (size_t)(p * 256 + nl) * E_ + s * 32 + u * 8;
    float4 v0 = ((const float4*)sp)[0];
    float4 v1 = ((const float4*)sp)[1];
    uint4 o;
    o.x = h2u(__floats2half2_rn(v0.x, v0.y));
    o.y = h2u(__floats2half2_rn(v0.z, v0.w));
    o.z = h2u(__floats2half2_rn(v1.x, v1.y));
    o.w = h2u(__floats2half2_rn(v1.z, v1.w));
    const int up = u ^ ((nl >> 1) & 3);
    *(uint4*)(dst + (size_t)mat * MAT + ((p * 16 + s) * 8192) + nl * 32 + up * 8) = o;
}

// ---------------- scatter messages + degree counts (vector red) -------------
__device__ __forceinline__ void red4(float* p, float a, float b, float c, float d) {
    asm volatile("red.global.add.v4.f32 [%0], {%1, %2, %3, %4};"
                 :: "l"(p), "f"(a), "f"(b), "f"(c), "f"(d) : "memory");
}

__device__ __forceinline__ float4 ld_half4(const __half* p, int o) {
    const __half2* q = (const __half2*)(p + o);
    float2 f0 = __half22float2(q[0]);
    float2 f1 = __half22float2(q[1]);
    return make_float4(f0.x, f0.y, f1.x, f1.y);
}

template<bool FIRST>
__global__ void scatter_upd(const int* __restrict__ head,
                            const int* __restrict__ tail,
                            const int* __restrict__ labels,
                            const int* __restrict__ concept_ids,
                            const int* __restrict__ relation_ids,
                            const __half* __restrict__ ctab,   // fp16 tables
                            const __half* __restrict__ rtab,
                            const __half* __restrict__ h16,
                            const __half* __restrict__ r16,
                            float* __restrict__ upd,
                            float* __restrict__ cnt) {
    const int t = blockIdx.x;
    if (labels[t] == -1) return;
    const int b  = t / MT;
    const size_t rowh = (size_t)b * MC + head[t];
    const size_t rowt = (size_t)b * MC + tail[t];

    const int i = threadIdx.x;                 // 0..127
    const int o = 4 * i;
    float4 hv, tv, rv;
    if (FIRST) {
        hv = ld_half4(ctab + (size_t)concept_ids[rowh] * E_, o);
        tv = ld_half4(ctab + (size_t)concept_ids[rowt] * E_, o);
        rv = ld_half4(rtab + (size_t)relation_ids[t] * E_, o);
    } else {
        hv = ld_half4(h16 + rowh * E_, o);
        tv = ld_half4(h16 + rowt * E_, o);
        rv = ld_half4(r16 + (size_t)t * E_, o);
    }
    float* ut = upd + rowt * E_;
    float* uh = upd + rowh * E_;
    red4(ut + o, hv.x - rv.x, hv.y - rv.y, hv.z - rv.z, hv.w - rv.w);
    red4(uh + o, tv.x - rv.x, tv.y - rv.y, tv.z - rv.z, tv.w - rv.w);
    if (i == 0) {
        atomicAdd(cnt + rowt, 1.0f);
        atomicAdd(cnt + rowh, 1.0f);
    }
}

// ==================== fp16 tensor-core GEMM NT (proven R9 core) ==============
// CTA 128x256, BK=32, double-buffered, 256 threads = 8 warps, 64x64 warp tiles.
template<int NSRC, bool RELU, bool A0HALF, bool CHALF>
__global__ __launch_bounds__(256, 1)
void gemm_fp16(const void* __restrict__ A0v, const int* __restrict__ ids0,
               const __half* __restrict__ Wf0,
               const float* __restrict__ A1, const __half* __restrict__ Wf1,
               const float* __restrict__ cnt,
               void* __restrict__ Cv, int ldc, int coff) {
    constexpr int KT = E_ / 32;                // 16 K-slices per source
    constexpr int TOTAL = NSRC * KT;

    __shared__ __align__(16) char sm[49152];   // As[2]:0,8K  Bs[2]:16K,32K
    const uint32_t sbase = (uint32_t)__cvta_generic_to_shared(sm);

    const int tid  = threadIdx.x;
    const int lane = tid & 31;
    const int wq   = tid >> 5;                 // warp 0..7
    const int wm   = (wq >> 2) * 64;
    const int wn   = (wq & 3) * 64;
    const int bm   = blockIdx.y * 128;
    const int bn   = blockIdx.x * 256;

    // ---- A staging: thread owns 4-elem chunk aj of rows ar+32*i, i=0..3 ----
    const int ar = tid >> 3;                   // 0..31
    const int aj = tid & 7;
    const int adst0 = ar * 64 + (((aj >> 1) ^ ((ar >> 1) & 3)) << 4) + ((aj & 1) << 3);
    const __half* Ah[4]; const float* Af[4]; const float* Au[4];
    float sc[4];
    #pragma unroll
    for (int i = 0; i < 4; ++i) {
        const int gr = bm + ar + 32 * i;
        const int gi = ids0 ? ids0[gr] : gr;
        if (A0HALF) Ah[i] = (const __half*)A0v + (size_t)gi * E_ + aj * 4;
        else        Af[i] = (const float*)A0v + (size_t)gi * E_ + aj * 4;
        if (NSRC == 2) {
            Au[i] = A1 + (size_t)gr * E_ + aj * 4;
            sc[i] = 1.0f / fmaxf(cnt[gr], 1.0f);
        }
    }

    // ---- B staging: 4 x uint4 of the 16KB pre-swizzled slice ----
    const __half* Bt0 = Wf0 + (size_t)blockIdx.x * 16 * 8192 + tid * 8;
    const __half* Bt1 = (NSRC == 2) ? (Wf1 + (size_t)blockIdx.x * 16 * 8192 + tid * 8) : nullptr;

    // ---- ldmatrix fragment offsets ----
    const int mloc  = (lane & 7) + ((lane >> 3) & 1) * 8;
    const int khalf = lane >> 4;
    int aoff[4][2], boff[4][2];
    #pragma unroll
    for (int f = 0; f < 4; ++f) {
        const int row = wm + f * 16 + mloc;
        const int sw  = (row >> 1) & 3;
        #pragma unroll
        for (int kk = 0; kk < 2; ++kk)
            aoff[f][kk] = row * 64 + ((((kk << 1) | khalf) ^ sw) << 4);
    }
    #pragma unroll
    for (int q = 0; q < 4; ++q) {
        const int row = wn + q * 16 + mloc;
        const int sw  = (row >> 1) & 3;
        #pragma unroll
        for (int kk = 0; kk < 2; ++kk)
            boff[q][kk] = row * 64 + ((((kk << 1) | khalf) ^ sw) << 4);
    }

    float4 la[4];
    uint2  lau[4];
    bool   conv = false;
    uint4  lb[4];

    float acc[4][8][4];
    #pragma unroll
    for (int f = 0; f < 4; ++f)
        #pragma unroll
        for (int g = 0; g < 8; ++g)
            #pragma unroll
            for (int e = 0; e < 4; ++e) acc[f][g][e] = 0.0f;

    auto ldg = [&](int t) {
        const bool sec = (NSRC == 2) && (t >= KT);
        const int s = t & (KT - 1);
        if (sec) {
            #pragma unroll
            for (int i = 0; i < 4; ++i) {
                la[i] = *(const float4*)(Au[i] + s * 32);
                la[i].x *= sc[i]; la[i].y *= sc[i];
                la[i].z *= sc[i]; la[i].w *= sc[i];
            }
            conv = true;
        } else if (A0HALF) {
            #pragma unroll
            for (int i = 0; i < 4; ++i) lau[i] = *(const uint2*)(Ah[i] + s * 32);
            conv = false;
        } else {
            #pragma unroll
            for (int i = 0; i < 4; ++i) la[i] = *(const float4*)(Af[i] + s * 32);
            conv = true;
        }
        const __half* bp = (sec ? Bt1 : Bt0) + (size_t)s * 8192;
        #pragma unroll
        for (int q = 0; q < 4; ++q) lb[q] = *(const uint4*)(bp + q * 2048);
    };

    auto sts = [&](int buf) {
        char* ab = sm + buf * 8192;
        #pragma unroll
        for (int i = 0; i < 4; ++i) {
            uint2 v;
            if (conv) {
                v.x = h2u(__floats2half2_rn(la[i].x, la[i].y));
                v.y = h2u(__floats2half2_rn(la[i].z, la[i].w));
            } else {
                v = lau[i];
            }
            *(uint2*)(ab + adst0 + i * 2048) = v;   // +32 rows = +2048 B
        }
        char* bb = sm + 16384 + buf * 16384;
        #pragma unroll
        for (int q = 0; q < 4; ++q)
            *(uint4*)(bb + tid * 16 + q * 4096) = lb[q];
    };

    auto compute = [&](int buf) {
        const uint32_t ab = sbase + buf * 8192;
        const uint32_t bb = sbase + 16384 + buf * 16384;
        #pragma unroll
        for (int kk = 0; kk < 2; ++kk) {
            uint32_t a[4][4];
            #pragma unroll
            for (int f = 0; f < 4; ++f) ldsm4(a[f], ab + aoff[f][kk]);
            #pragma unroll
            for (int q = 0; q < 4; ++q) {
                uint32_t b[4];
                ldsm4(b, bb + boff[q][kk]);
                #pragma unroll
                for (int f = 0; f < 4; ++f) {
                    mma_fp16(acc[f][q * 2 + 0], a[f], b[0], b[2]);
                    mma_fp16(acc[f][q * 2 + 1], a[f], b[1], b[3]);
                }
            }
        }
    };

    // ---- pipeline ----
    ldg(0);
    sts(0);
    __syncthreads();
    for (int t = 0; t < TOTAL; ++t) {
        const int buf = t & 1;
        if (t + 1 < TOTAL) ldg(t + 1);
        compute(buf);
        if (t + 1 < TOTAL) {
            sts(buf ^ 1);
            __syncthreads();
        }
    }

    // ---- epilogue: warp tile 64x64 ----
    #pragma unroll
    for (int f = 0; f < 4; ++f) {
        #pragma unroll
        for (int g = 0; g < 8; ++g) {
            const int row0 = bm + wm + f * 16 + (lane >> 2);
            const int col  = wn + g * 8 + (lane & 3) * 2;
            float2 v0 = make_float2(acc[f][g][0], acc[f][g][1]);
            float2 v1 = make_float2(acc[f][g][2], acc[f][g][3]);
            if (RELU) {
                v0.x = fmaxf(v0.x, 0.f); v0.y = fmaxf(v0.y, 0.f);
                v1.x = fmaxf(v1.x, 0.f); v1.y = fmaxf(v1.y, 0.f);
            }
            if (CHALF) {
                __half* Ch = (__half*)Cv;
                *(uint32_t*)&Ch[(size_t)row0 * E_ + bn + col] =
                    h2u(__floats2half2_rn(v0.x, v0.y));
                *(uint32_t*)&Ch[(size_t)(row0 + 8) * E_ + bn + col] =
                    h2u(__floats2half2_rn(v1.x, v1.y));
            } else {
                float* Cf = (float*)Cv;
                *(float2*)&Cf[(size_t)row0 * ldc + coff + bn + col]       = v0;
                *(float2*)&Cf[(size_t)(row0 + 8) * ldc + coff + bn + col] = v1;
            }
        }
    }
}

// ---------------- final: out[t] = [h2[head], (r written by GEMM), h2[tail]] --
__global__ void final_gather_ht(const __half* __restrict__ h2,
                                const int* __restrict__ head,
                                const int* __restrict__ tail,
                                float* __restrict__ out) {
    const int t = blockIdx.x;
    const int b = t / MT;
    const __half* hh = h2 + ((size_t)b * MC + head[t]) * E_;
    const __half* ht = h2 + ((size_t)b * MC + tail[t]) * E_;
    float4* o = (float4*)(out + (size_t)t * 3 * E_);
    const int i = threadIdx.x;                 // 0..127
    const int off = 4 * i;
    o[i]       = ld_half4(hh, off);
    o[256 + i] = ld_half4(ht, off);
}

// ---------------- host launch ------------------------------------------------
extern "C" void kernel_launch(void* const* d_in, const int* in_sizes, int n_in,
                              void* d_out, int out_size) {
    const float* concept_table  = (const float*)d_in[0];
    const float* relation_table = (const float*)d_in[1];
    const float* W_s            = (const float*)d_in[2];
    const float* W_n            = (const float*)d_in[3];
    const float* W_r            = (const float*)d_in[4];
    const int*   concept_ids    = (const int*)d_in[5];
    const int*   relation_ids   = (const int*)d_in[6];
    const int*   head_idx       = (const int*)d_in[7];
    const int*   tail_idx       = (const int*)d_in[8];
    const int*   labels         = (const int*)d_in[9];
    float*       out            = (float*)d_out;

    __half *ct16, *rt16, *h16, *r16, *h2h, *wf;
    float *upd0, *upd1;
    cudaGetSymbolAddress((void**)&ct16, g_ct16);
    cudaGetSymbolAddress((void**)&rt16, g_rt16);
    cudaGetSymbolAddress((void**)&h16,  g_h16);
    cudaGetSymbolAddress((void**)&r16,  g_r16);
    cudaGetSymbolAddress((void**)&h2h,  g_h2h);
    cudaGetSymbolAddress((void**)&upd0, g_upd0);
    cudaGetSymbolAddress((void**)&upd1, g_upd1);
    cudaGetSymbolAddress((void**)&wf,   g_wf);
    float* cnt0 = upd0 + (size_t)NROW_H * E_;
    float* cnt1 = upd1 + (size_t)NROW_H * E_;

    cudaStream_t s2;
    cudaStreamCreateWithFlags(&s2, cudaStreamNonBlocking);
    cudaEvent_t eStart, eM0, eT16, eR16, eJoin1;
    cudaEventCreateWithFlags(&eStart, cudaEventDisableTiming);
    cudaEventCreateWithFlags(&eM0,    cudaEventDisableTiming);
    cudaEventCreateWithFlags(&eT16,   cudaEventDisableTiming);
    cudaEventCreateWithFlags(&eR16,   cudaEventDisableTiming);
    cudaEventCreateWithFlags(&eJoin1, cudaEventDisableTiming);

    const dim3 gh(E_ / 256, NROW_H / 128);      // (2, 256)
    const dim3 gr(E_ / 256, NROW_R / 128);      // (2, 512)
    const size_t UPD_BYTES = sizeof(float) * ((size_t)NROW_H * E_ + NROW_H);

    // ---- fork: side stream clears both upd buffers while main preps --------
    cudaEventRecord(eStart, 0);
    cudaStreamWaitEvent(s2, eStart, 0);
    cudaMemsetAsync(upd0, 0, UPD_BYTES, s2);
    cudaMemsetAsync(upd1, 0, UPD_BYTES, s2);
    cudaEventRecord(eM0, s2);

    // ---- main: table + weight prep ------------------------------------------
    to_half<<<(VOCAB * E_ / 8 + 255) / 256, 256>>>(concept_table, ct16, VOCAB * E_ / 8);
    to_half<<<(NREL * E_ / 8 + 255) / 256, 256>>>(relation_table, rt16, NREL * E_ / 8);
    prep_weights<<<6 * MAT / 8 / 256, 256>>>(W_s, W_n, W_r, wf);
    cudaEventRecord(eT16, 0);

    // ---- side stream: the whole r-chain (rgemm0 -> rgemm1 -> out slice 1) ---
    cudaStreamWaitEvent(s2, eT16, 0);
    gemm_fp16<1, false, true, true><<<gr, 256, 0, s2>>>(
        rt16, relation_ids, wf + 4 * (size_t)MAT,
        nullptr, nullptr, nullptr, r16, E_, 0);
    cudaEventRecord(eR16, s2);
    gemm_fp16<1, false, true, false><<<gr, 256, 0, s2>>>(
        r16, nullptr, wf + 5 * (size_t)MAT,
        nullptr, nullptr, nullptr, out, 3 * E_, E_);
    cudaEventRecord(eJoin1, s2);

    // ---- main: hop-0 h-chain -------------------------------------------------
    cudaStreamWaitEvent(0, eM0, 0);
    scatter_upd<true><<<NROW_R, 128>>>(head_idx, tail_idx, labels,
                                       concept_ids, relation_ids,
                                       ct16, rt16, nullptr, nullptr,
                                       upd0, cnt0);
    gemm_fp16<2, true, true, true><<<gh, 256>>>(
        ct16, concept_ids, wf + 0 * (size_t)MAT,
        upd0, wf + 2 * (size_t)MAT, cnt0, h16, E_, 0);

    // ---- main: hop-1 h-chain (needs r16 from the side stream) ---------------
    cudaStreamWaitEvent(0, eR16, 0);
    scatter_upd<false><<<NROW_R, 128>>>(head_idx, tail_idx, labels,
                                        concept_ids, relation_ids,
                                        nullptr, nullptr, h16, r16,
                                        upd1, cnt1);
    gemm_fp16<2, true, true, true><<<gh, 256>>>(
        h16, nullptr, wf + 1 * (size_t)MAT,
        upd1, wf + 3 * (size_t)MAT, cnt1, h2h, E_, 0);
    final_gather_ht<<<NROW_R, 128>>>(h2h, head_idx, tail_idx, out);

    // ---- join ----------------------------------------------------------------
    cudaStreamWaitEvent(0, eJoin1, 0);
}

// round 12
// speedup vs baseline: 3.2177x; 1.1625x over previous
#include <cuda_runtime.h>
#include <cuda_fp16.h>
#include <cstdint>
#include <cstring>

// Problem constants (fixed by the dataset)
#define B_    16
#define MC    2048
#define MT    4096
#define E_    512
#define VOCAB 32000
#define NREL  69

#define NROW_H (B_ * MC)   // 32768
#define NROW_R (B_ * MT)   // 65536
#define MAT    (E_ * E_)   // 262144

// ---------------- scratch (static device globals; no allocation allowed) ---
__device__ __half g_ct16[VOCAB * E_];            // fp16 concept table
__device__ __half g_rt16[NREL * E_];             // fp16 relation table
__device__ __half g_wr16[2 * MAT];               // fp16 plain Wr0, Wr1
__device__ __half g_R0h [NREL * E_];             // r embeddings after hop 0
__device__ float  g_R1f [NREL * E_];             // r embeddings after hop 1
__device__ __half g_h16[NROW_H * E_];            // h after hop 0 (fp16)
__device__ __half g_h2h[NROW_H * E_];            // h after hop 1 (fp16)
__device__ float  g_upd0[NROW_H * E_ + NROW_H];  // hop-0 upd (+cnt tail)
__device__ float  g_upd1[NROW_H * E_ + NROW_H];  // hop-1 upd (+cnt tail)
__device__ __half g_wf [4 * MAT];                // fp16 pre-swizzled weights
                                                 // [Ws0,Ws1,Wn0,Wn1]

// ---------------- bit-cast helper --------------------------------------------
__device__ __forceinline__ uint32_t h2u(__half2 v) {
    uint32_t r;
    memcpy(&r, &v, 4);
    return r;
}

// ---------------- mma / ldmatrix helpers -------------------------------------
__device__ __forceinline__ void ldsm4(uint32_t* r, uint32_t addr) {
    asm volatile("ldmatrix.sync.aligned.m8n8.x4.shared.b16 {%0,%1,%2,%3}, [%4];"
                 : "=r"(r[0]), "=r"(r[1]), "=r"(r[2]), "=r"(r[3]) : "r"(addr));
}

__device__ __forceinline__ void mma_fp16(float* c, const uint32_t* a,
                                         uint32_t b0, uint32_t b1) {
    asm volatile(
        "mma.sync.aligned.m16n8k16.row.col.f32.f16.f16.f32 "
        "{%0,%1,%2,%3}, {%4,%5,%6,%7}, {%8,%9}, {%0,%1,%2,%3};\n"
        : "+f"(c[0]), "+f"(c[1]), "+f"(c[2]), "+f"(c[3])
        : "r"(a[0]), "r"(a[1]), "r"(a[2]), "r"(a[3]), "r"(b0), "r"(b1));
}

// ---------------- fp32 -> fp16 conversion ------------------------------------
__global__ void to_half(const float* __restrict__ src, __half* __restrict__ dst,
                        int n8) {
    const int i = blockIdx.x * 256 + threadIdx.x;   // one 8-elem chunk each
    if (i >= n8) return;
    float4 a = ((const float4*)src)[2 * i];
    float4 b = ((const float4*)src)[2 * i + 1];
    uint4 o;
    o.x = h2u(__floats2half2_rn(a.x, a.y));
    o.y = h2u(__floats2half2_rn(a.z, a.w));
    o.z = h2u(__floats2half2_rn(b.x, b.y));
    o.w = h2u(__floats2half2_rn(b.z, b.w));
    ((uint4*)dst)[i] = o;
}

// ---------------- weight prep: fp32 row-major -> fp16 pre-swizzled tiles ----
// Only Ws0,Ws1,Wn0,Wn1 (the big h-GEMMs). Layout as in prior rounds.
__global__ void prep_weights(const float* __restrict__ Ws,
                             const float* __restrict__ Wn,
                             __half* __restrict__ dst) {
    const int idx = blockIdx.x * 256 + threadIdx.x;   // one 16B unit each
    const int mat  = idx >> 15;                       // 0..3
    const int rem  = idx & 32767;
    const int p    = rem >> 14;
    const int s    = (rem >> 10) & 15;
    const int nl   = (rem >> 2) & 255;
    const int u    = rem & 3;
    const float* src = (mat < 2) ? Ws + (size_t)mat * MAT
                                 : Wn + (size_t)(mat - 2) * MAT;
    const float* sp = src + (size_t)(p * 256 + nl) * E_ + s * 32 + u * 8;
    float4 v0 = ((const float4*)sp)[0];
    float4 v1 = ((const float4*)sp)[1];
    uint4 o;
    o.x = h2u(__floats2half2_rn(v0.x, v0.y));
    o.y = h2u(__floats2half2_rn(v0.z, v0.w));
    o.z = h2u(__floats2half2_rn(v1.x, v1.y));
    o.w = h2u(__floats2half2_rn(v1.z, v1.w));
    const int up = u ^ ((nl >> 1) & 3);
    *(uint4*)(dst + (size_t)mat * MAT + ((p * 16 + s) * 8192) + nl * 32 + up * 8) = o;
}

// ---------------- tiny r-GEMM: out[row][n] = sum_k A[row][k] * W[n][k] -------
// rows = NREL (69). One block per row, 512 threads = one output column each.
// fp16 inputs, fp32 accumulate -- same rounding points as the big GEMM path.
template<bool OUT16>
__global__ void __launch_bounds__(512)
small_gemm(const __half* __restrict__ A, const __half* __restrict__ W,
           __half* __restrict__ out16, float* __restrict__ out32) {
    __shared__ float arow[E_];
    const int row = blockIdx.x;
    const int n   = threadIdx.x;
    if (n < 256) {
        float2 f = __half22float2(((const __half2*)(A + (size_t)row * E_))[n]);
        arow[2 * n]     = f.x;
        arow[2 * n + 1] = f.y;
    }
    __syncthreads();
    const __half2* w2 = (const __half2*)(W + (size_t)n * E_);
    float s = 0.0f;
    #pragma unroll 16
    for (int k = 0; k < E_ / 2; ++k) {
        float2 wf = __half22float2(w2[k]);
        s += arow[2 * k] * wf.x + arow[2 * k + 1] * wf.y;
    }
    if (OUT16) out16[(size_t)row * E_ + n] = __float2half_rn(s);
    else       out32[(size_t)row * E_ + n] = s;
}

// ---------------- scatter messages + degree counts (vector red) -------------
__device__ __forceinline__ void red4(float* p, float a, float b, float c, float d) {
    asm volatile("red.global.add.v4.f32 [%0], {%1, %2, %3, %4};"
                 :: "l"(p), "f"(a), "f"(b), "f"(c), "f"(d) : "memory");
}

__device__ __forceinline__ float4 ld_half4(const __half* p, int o) {
    const __half2* q = (const __half2*)(p + o);
    float2 f0 = __half22float2(q[0]);
    float2 f1 = __half22float2(q[1]);
    return make_float4(f0.x, f0.y, f1.x, f1.y);
}

// FIRST: h rows via concept_ids indirection into ct16; else h16 rows direct.
// r rows ALWAYS rtab[relation_ids[t]] (rtab = rt16 for hop 0, R0h for hop 1).
template<bool FIRST>
__global__ void scatter_upd(const int* __restrict__ head,
                            const int* __restrict__ tail,
                            const int* __restrict__ labels,
                            const int* __restrict__ concept_ids,
                            const int* __restrict__ relation_ids,
                            const __half* __restrict__ ctab,
                            const __half* __restrict__ h16,
                            const __half* __restrict__ rtab,
                            float* __restrict__ upd,
                            float* __restrict__ cnt) {
    const int t = blockIdx.x;
    if (labels[t] == -1) return;
    const int b  = t / MT;
    const size_t rowh = (size_t)b * MC + head[t];
    const size_t rowt = (size_t)b * MC + tail[t];

    const int i = threadIdx.x;                 // 0..127
    const int o = 4 * i;
    float4 hv, tv;
    if (FIRST) {
        hv = ld_half4(ctab + (size_t)concept_ids[rowh] * E_, o);
        tv = ld_half4(ctab + (size_t)concept_ids[rowt] * E_, o);
    } else {
        hv = ld_half4(h16 + rowh * E_, o);
        tv = ld_half4(h16 + rowt * E_, o);
    }
    float4 rv = ld_half4(rtab + (size_t)relation_ids[t] * E_, o);
    float* ut = upd + rowt * E_;
    float* uh = upd + rowh * E_;
    red4(ut + o, hv.x - rv.x, hv.y - rv.y, hv.z - rv.z, hv.w - rv.w);
    red4(uh + o, tv.x - rv.x, tv.y - rv.y, tv.z - rv.z, tv.w - rv.w);
    if (i == 0) {
        atomicAdd(cnt + rowt, 1.0f);
        atomicAdd(cnt + rowh, 1.0f);
    }
}

// ==================== fp16 tensor-core GEMM NT (proven R9 core) ==============
// CTA 128x256, BK=32, double-buffered, 256 threads = 8 warps, 64x64 warp tiles.
template<int NSRC, bool RELU, bool A0HALF, bool CHALF>
__global__ __launch_bounds__(256, 1)
void gemm_fp16(const void* __restrict__ A0v, const int* __restrict__ ids0,
               const __half* __restrict__ Wf0,
               const float* __restrict__ A1, const __half* __restrict__ Wf1,
               const float* __restrict__ cnt,
               void* __restrict__ Cv, int ldc, int coff) {
    constexpr int KT = E_ / 32;                // 16 K-slices per source
    constexpr int TOTAL = NSRC * KT;

    __shared__ __align__(16) char sm[49152];   // As[2]:0,8K  Bs[2]:16K,32K
    const uint32_t sbase = (uint32_t)__cvta_generic_to_shared(sm);

    const int tid  = threadIdx.x;
    const int lane = tid & 31;
    const int wq   = tid >> 5;                 // warp 0..7
    const int wm   = (wq >> 2) * 64;
    const int wn   = (wq & 3) * 64;
    const int bm   = blockIdx.y * 128;
    const int bn   = blockIdx.x * 256;

    // ---- A staging: thread owns 4-elem chunk aj of rows ar+32*i, i=0..3 ----
    const int ar = tid >> 3;                   // 0..31
    const int aj = tid & 7;
    const int adst0 = ar * 64 + (((aj >> 1) ^ ((ar >> 1) & 3)) << 4) + ((aj & 1) << 3);
    const __half* Ah[4]; const float* Af[4]; const float* Au[4];
    float sc[4];
    #pragma unroll
    for (int i = 0; i < 4; ++i) {
        const int gr = bm + ar + 32 * i;
        const int gi = ids0 ? ids0[gr] : gr;
        if (A0HALF) Ah[i] = (const __half*)A0v + (size_t)gi * E_ + aj * 4;
        else        Af[i] = (const float*)A0v + (size_t)gi * E_ + aj * 4;
        if (NSRC == 2) {
            Au[i] = A1 + (size_t)gr * E_ + aj * 4;
            sc[i] = 1.0f / fmaxf(cnt[gr], 1.0f);
        }
    }

    // ---- B staging: 4 x uint4 of the 16KB pre-swizzled slice ----
    const __half* Bt0 = Wf0 + (size_t)blockIdx.x * 16 * 8192 + tid * 8;
    const __half* Bt1 = (NSRC == 2) ? (Wf1 + (size_t)blockIdx.x * 16 * 8192 + tid * 8) : nullptr;

    // ---- ldmatrix fragment offsets ----
    const int mloc  = (lane & 7) + ((lane >> 3) & 1) * 8;
    const int khalf = lane >> 4;
    int aoff[4][2], boff[4][2];
    #pragma unroll
    for (int f = 0; f < 4; ++f) {
        const int row = wm + f * 16 + mloc;
        const int sw  = (row >> 1) & 3;
        #pragma unroll
        for (int kk = 0; kk < 2; ++kk)
            aoff[f][kk] = row * 64 + ((((kk << 1) | khalf) ^ sw) << 4);
    }
    #pragma unroll
    for (int q = 0; q < 4; ++q) {
        const int row = wn + q * 16 + mloc;
        const int sw  = (row >> 1) & 3;
        #pragma unroll
        for (int kk = 0; kk < 2; ++kk)
            boff[q][kk] = row * 64 + ((((kk << 1) | khalf) ^ sw) << 4);
    }

    float4 la[4];
    uint2  lau[4];
    bool   conv = false;
    uint4  lb[4];

    float acc[4][8][4];
    #pragma unroll
    for (int f = 0; f < 4; ++f)
        #pragma unroll
        for (int g = 0; g < 8; ++g)
            #pragma unroll
            for (int e = 0; e < 4; ++e) acc[f][g][e] = 0.0f;

    auto ldg = [&](int t) {
        const bool sec = (NSRC == 2) && (t >= KT);
        const int s = t & (KT - 1);
        if (sec) {
            #pragma unroll
            for (int i = 0; i < 4; ++i) {
                la[i] = *(const float4*)(Au[i] + s * 32);
                la[i].x *= sc[i]; la[i].y *= sc[i];
                la[i].z *= sc[i]; la[i].w *= sc[i];
            }
            conv = true;
        } else if (A0HALF) {
            #pragma unroll
            for (int i = 0; i < 4; ++i) lau[i] = *(const uint2*)(Ah[i] + s * 32);
            conv = false;
        } else {
            #pragma unroll
            for (int i = 0; i < 4; ++i) la[i] = *(const float4*)(Af[i] + s * 32);
            conv = true;
        }
        const __half* bp = (sec ? Bt1 : Bt0) + (size_t)s * 8192;
        #pragma unroll
        for (int q = 0; q < 4; ++q) lb[q] = *(const uint4*)(bp + q * 2048);
    };

    auto sts = [&](int buf) {
        char* ab = sm + buf * 8192;
        #pragma unroll
        for (int i = 0; i < 4; ++i) {
            uint2 v;
            if (conv) {
                v.x = h2u(__floats2half2_rn(la[i].x, la[i].y));
                v.y = h2u(__floats2half2_rn(la[i].z, la[i].w));
            } else {
                v = lau[i];
            }
            *(uint2*)(ab + adst0 + i * 2048) = v;   // +32 rows = +2048 B
        }
        char* bb = sm + 16384 + buf * 16384;
        #pragma unroll
        for (int q = 0; q < 4; ++q)
            *(uint4*)(bb + tid * 16 + q * 4096) = lb[q];
    };

    auto compute = [&](int buf) {
        const uint32_t ab = sbase + buf * 8192;
        const uint32_t bb = sbase + 16384 + buf * 16384;
        #pragma unroll
        for (int kk = 0; kk < 2; ++kk) {
            uint32_t a[4][4];
            #pragma unroll
            for (int f = 0; f < 4; ++f) ldsm4(a[f], ab + aoff[f][kk]);
            #pragma unroll
            for (int q = 0; q < 4; ++q) {
                uint32_t b[4];
                ldsm4(b, bb + boff[q][kk]);
                #pragma unroll
                for (int f = 0; f < 4; ++f) {
                    mma_fp16(acc[f][q * 2 + 0], a[f], b[0], b[2]);
                    mma_fp16(acc[f][q * 2 + 1], a[f], b[1], b[3]);
                }
            }
        }
    };

    // ---- pipeline ----
    ldg(0);
    sts(0);
    __syncthreads();
    for (int t = 0; t < TOTAL; ++t) {
        const int buf = t & 1;
        if (t + 1 < TOTAL) ldg(t + 1);
        compute(buf);
        if (t + 1 < TOTAL) {
            sts(buf ^ 1);
            __syncthreads();
        }
    }

    // ---- epilogue: warp tile 64x64 ----
    #pragma unroll
    for (int f = 0; f < 4; ++f) {
        #pragma unroll
        for (int g = 0; g < 8; ++g) {
            const int row0 = bm + wm + f * 16 + (lane >> 2);
            const int col  = wn + g * 8 + (lane & 3) * 2;
            float2 v0 = make_float2(acc[f][g][0], acc[f][g][1]);
            float2 v1 = make_float2(acc[f][g][2], acc[f][g][3]);
            if (RELU) {
                v0.x = fmaxf(v0.x, 0.f); v0.y = fmaxf(v0.y, 0.f);
                v1.x = fmaxf(v1.x, 0.f); v1.y = fmaxf(v1.y, 0.f);
            }
            if (CHALF) {
                __half* Ch = (__half*)Cv;
                *(uint32_t*)&Ch[(size_t)row0 * E_ + bn + col] =
                    h2u(__floats2half2_rn(v0.x, v0.y));
                *(uint32_t*)&Ch[(size_t)(row0 + 8) * E_ + bn + col] =
                    h2u(__floats2half2_rn(v1.x, v1.y));
            } else {
                float* Cf = (float*)Cv;
                *(float2*)&Cf[(size_t)row0 * ldc + coff + bn + col]       = v0;
                *(float2*)&Cf[(size_t)(row0 + 8) * ldc + coff + bn + col] = v1;
            }
        }
    }
}

// ---------------- final: out[t] = [h2h[head], R1[rel], h2h[tail]] -----------
__global__ void final_gather3(const __half* __restrict__ h2,
                              const float* __restrict__ R1,
                              const int* __restrict__ head,
                              const int* __restrict__ tail,
                              const int* __restrict__ relation_ids,
                              float* __restrict__ out) {
    const int t = blockIdx.x;
    const int b = t / MT;
    const __half* hh = h2 + ((size_t)b * MC + head[t]) * E_;
    const __half* ht = h2 + ((size_t)b * MC + tail[t]) * E_;
    const float4* rr = (const float4*)(R1 + (size_t)relation_ids[t] * E_);
    float4* o = (float4*)(out + (size_t)t * 3 * E_);
    const int i = threadIdx.x;                 // 0..127
    const int off = 4 * i;
    o[i]       = ld_half4(hh, off);
    o[128 + i] = rr[i];
    o[256 + i] = ld_half4(ht, off);
}

// ---------------- host launch ------------------------------------------------
extern "C" void kernel_launch(void* const* d_in, const int* in_sizes, int n_in,
                              void* d_out, int out_size) {
    const float* concept_table  = (const float*)d_in[0];
    const float* relation_table = (const float*)d_in[1];
    const float* W_s            = (const float*)d_in[2];
    const float* W_n            = (const float*)d_in[3];
    const float* W_r            = (const float*)d_in[4];
    const int*   concept_ids    = (const int*)d_in[5];
    const int*   relation_ids   = (const int*)d_in[6];
    const int*   head_idx       = (const int*)d_in[7];
    const int*   tail_idx       = (const int*)d_in[8];
    const int*   labels         = (const int*)d_in[9];
    float*       out            = (float*)d_out;

    __half *ct16, *rt16, *wr16, *R0h, *h16, *h2h, *wf;
    float *R1f, *upd0, *upd1;
    cudaGetSymbolAddress((void**)&ct16, g_ct16);
    cudaGetSymbolAddress((void**)&rt16, g_rt16);
    cudaGetSymbolAddress((void**)&wr16, g_wr16);
    cudaGetSymbolAddress((void**)&R0h,  g_R0h);
    cudaGetSymbolAddress((void**)&R1f,  g_R1f);
    cudaGetSymbolAddress((void**)&h16,  g_h16);
    cudaGetSymbolAddress((void**)&h2h,  g_h2h);
    cudaGetSymbolAddress((void**)&upd0, g_upd0);
    cudaGetSymbolAddress((void**)&upd1, g_upd1);
    cudaGetSymbolAddress((void**)&wf,   g_wf);
    float* cnt0 = upd0 + (size_t)NROW_H * E_;
    float* cnt1 = upd1 + (size_t)NROW_H * E_;

    cudaStream_t s2;
    cudaStreamCreateWithFlags(&s2, cudaStreamNonBlocking);
    cudaEvent_t eStart, eM0, eT16, eR0, eR1;
    cudaEventCreateWithFlags(&eStart, cudaEventDisableTiming);
    cudaEventCreateWithFlags(&eM0,    cudaEventDisableTiming);
    cudaEventCreateWithFlags(&eT16,   cudaEventDisableTiming);
    cudaEventCreateWithFlags(&eR0,    cudaEventDisableTiming);
    cudaEventCreateWithFlags(&eR1,    cudaEventDisableTiming);

    const dim3 gh(E_ / 256, NROW_H / 128);      // (2, 256)
    const size_t UPD_BYTES = sizeof(float) * ((size_t)NROW_H * E_ + NROW_H);

    // ---- side stream: memsets up front, then the tiny r-chain ---------------
    cudaEventRecord(eStart, 0);
    cudaStreamWaitEvent(s2, eStart, 0);
    cudaMemsetAsync(upd0, 0, UPD_BYTES, s2);
    cudaMemsetAsync(upd1, 0, UPD_BYTES, s2);
    cudaEventRecord(eM0, s2);

    // ---- main: table + weight prep ------------------------------------------
    to_half<<<(VOCAB * E_ / 8 + 255) / 256, 256>>>(concept_table, ct16, VOCAB * E_ / 8);
    to_half<<<(NREL * E_ / 8 + 255) / 256, 256>>>(relation_table, rt16, NREL * E_ / 8);
    to_half<<<(2 * MAT / 8 + 255) / 256, 256>>>(W_r, wr16, 2 * MAT / 8);
    prep_weights<<<4 * MAT / 8 / 256, 256>>>(W_s, W_n, wf);
    cudaEventRecord(eT16, 0);

    // side stream: R0 = rt16 @ Wr0^T (fp16), R1 = R0 @ Wr1^T (fp32)
    cudaStreamWaitEvent(s2, eT16, 0);
    small_gemm<true ><<<NREL, 512, 0, s2>>>(rt16, wr16,       R0h, nullptr);
    cudaEventRecord(eR0, s2);
    small_gemm<false><<<NREL, 512, 0, s2>>>(R0h,  wr16 + MAT, nullptr, R1f);
    cudaEventRecord(eR1, s2);

    // ---- main: hop-0 h-chain -------------------------------------------------
    cudaStreamWaitEvent(0, eM0, 0);
    scatter_upd<true><<<NROW_R, 128>>>(head_idx, tail_idx, labels,
                                       concept_ids, relation_ids,
                                       ct16, nullptr, rt16, upd0, cnt0);
    gemm_fp16<2, true, true, true><<<gh, 256>>>(
        ct16, concept_ids, wf + 0 * (size_t)MAT,
        upd0, wf + 2 * (size_t)MAT, cnt0, h16, E_, 0);

    // ---- main: hop-1 h-chain (needs R0 from the side stream) ----------------
    cudaStreamWaitEvent(0, eR0, 0);
    scatter_upd<false><<<NROW_R, 128>>>(head_idx, tail_idx, labels,
                                        concept_ids, relation_ids,
                                        nullptr, h16, R0h, upd1, cnt1);
    gemm_fp16<2, true, true, true><<<gh, 256>>>(
        h16, nullptr, wf + 1 * (size_t)MAT,
        upd1, wf + 3 * (size_t)MAT, cnt1, h2h, E_, 0);

    // ---- final: all three output slices (needs R1) ---------------------------
    cudaStreamWaitEvent(0, eR1, 0);
    final_gather3<<<NROW_R, 128>>>(h2h, R1f, head_idx, tail_idx,
                                   relation_ids, out);
}